// round 13
// baseline (speedup 1.0000x reference)
#include <cuda_runtime.h>
#include <math.h>
#include <stdint.h>

#define BATCH   2
#define SEQLEN  1024
#define DMODEL  1024
#define DINNER  2048
#define NSTATE  16
#define BL      (BATCH*SEQLEN)      // 2048 rows
#define XPROJ_ROWS 33               // 1 dt + 16 B + 16 C
#define NCHUNK  16
#define LC      (SEQLEN/NCHUNK)     // 64
#define NPAIR   (BATCH*DINNER/2)    // 2048 warp-pairs
#define PGRID   296                 // persistent GEMM grid (148 SMs x 2 CTAs)

// ---------------- scratch (no allocs allowed) ----------------
__device__ float g_xz[(size_t)BL * 2 * DINNER];   // [bl][4096]
__device__ float g_xc[(size_t)BL * DINNER];       // conv out; later split-K partial 2
__device__ float g_xp[(size_t)BL * XPROJ_ROWS];
__device__ float g_xp2[(size_t)BL * XPROJ_ROWS];  // xproj K-split partial
__device__ float g_pk[(size_t)BL * DINNER];       // split-K partials 0,1
// transposed [b][d][t] scan streams
__device__ float g_dtT[(size_t)BL * DINNER];
__device__ float g_xcT[(size_t)BL * DINNER];
__device__ float g_gateT[(size_t)BL * DINNER];
__device__ float g_ygT[(size_t)BL * DINNER];
// TF32-rounded copies of GEMM inputs (g_xr later split-K partial 3)
__device__ float g_xr[(size_t)BL * DMODEL];
__device__ float g_w1r[(size_t)(2*DINNER) * DMODEL];
__device__ float g_w2r[(size_t)DMODEL * DINNER];
// chunked-scan scratch
__device__ float g_S [(size_t)NPAIR * (NCHUNK-1) * 2];
__device__ float g_Lh[(size_t)NPAIR * (NCHUNK-1) * 32];
__device__ float g_Hin[(size_t)NPAIR * NCHUNK * 32];

__device__ __forceinline__ unsigned f2tf32(float x) {
    unsigned r;
    asm("cvt.rna.tf32.f32 %0, %1;" : "=r"(r) : "f"(x));
    return r;
}

// ---------------- fused RNA pre-rounding ----------------
#define XN4   ((BL * DMODEL) / 4)
#define W1N4  ((2 * DINNER * DMODEL) / 4)
#define W2N4  ((DMODEL * DINNER) / 4)
__global__ __launch_bounds__(256) void rna_round_all(const float* __restrict__ x,
                                                     const float* __restrict__ w1,
                                                     const float* __restrict__ w2) {
    int i = blockIdx.x * 256 + threadIdx.x;
    const float4* src;
    float4* dst;
    int off;
    if (i < XN4)              { src = (const float4*)x;  dst = (float4*)g_xr;  off = i; }
    else if (i < XN4 + W1N4)  { src = (const float4*)w1; dst = (float4*)g_w1r; off = i - XN4; }
    else if (i < XN4 + W1N4 + W2N4) { src = (const float4*)w2; dst = (float4*)g_w2r; off = i - XN4 - W1N4; }
    else return;
    float4 v = src[off];
    v.x = __uint_as_float(f2tf32(v.x));
    v.y = __uint_as_float(f2tf32(v.y));
    v.z = __uint_as_float(f2tf32(v.z));
    v.w = __uint_as_float(f2tf32(v.w));
    dst[off] = v;
}

// ---------------- add pass for split-K=4 ----------------
__global__ __launch_bounds__(256) void add4_kernel(const float* __restrict__ p0,
                                                   const float* __restrict__ p1,
                                                   const float* __restrict__ p2,
                                                   const float* __restrict__ p3,
                                                   float* __restrict__ out, int n4) {
    int i = blockIdx.x * 256 + threadIdx.x;
    if (i >= n4) return;
    float4 a = ((const float4*)p0)[i];
    float4 b = ((const float4*)p1)[i];
    float4 c = ((const float4*)p2)[i];
    float4 d = ((const float4*)p3)[i];
    ((float4*)out)[i] = make_float4((a.x + b.x) + (c.x + d.x),
                                    (a.y + b.y) + (c.y + d.y),
                                    (a.z + b.z) + (c.z + d.z),
                                    (a.w + b.w) + (c.w + d.w));
}

// ================= common GEMM helpers =================
#define BK      16
#define KPITCH  20
#define ATILE   (128 * KPITCH)
#define STAGE_F (2 * ATILE)
#define STAGES  4
#define GSMEM   (STAGES * STAGE_F * 4)   // 81920 B

__device__ __forceinline__ uint32_t smem_u32(const void* p) {
    uint32_t a;
    asm("{ .reg .u64 t; cvta.to.shared.u64 t, %1; cvt.u32.u64 %0, t; }" : "=r"(a) : "l"(p));
    return a;
}
__device__ __forceinline__ void cp_async16(uint32_t dst, const void* src) {
    asm volatile("cp.async.cg.shared.global [%0], [%1], 16;" :: "r"(dst), "l"(src));
}
__device__ __forceinline__ void cp_commit() {
    asm volatile("cp.async.commit_group;");
}
template <int N>
__device__ __forceinline__ void cp_wait() {
    asm volatile("cp.async.wait_group %0;" :: "n"(N));
}
__device__ __forceinline__ void mma_tf32(float* c, const unsigned* a, const unsigned* b) {
    asm volatile(
        "mma.sync.aligned.m16n8k8.row.col.f32.tf32.tf32.f32 "
        "{%0,%1,%2,%3}, {%4,%5,%6,%7}, {%8,%9}, {%0,%1,%2,%3};\n"
        : "+f"(c[0]), "+f"(c[1]), "+f"(c[2]), "+f"(c[3])
        : "r"(a[0]), "r"(a[1]), "r"(a[2]), "r"(a[3]), "r"(b[0]), "r"(b[1]));
}

// ================= GEMM1 (A row-major), persistent tile loop =================
__global__ __launch_bounds__(256, 2) void gemm_tf32_pipe(const float* __restrict__ A,
                                                         const float* __restrict__ B,
                                                         float* __restrict__ C,
                                                         int M, int N, int K) {
    extern __shared__ float smem[];
    const uint32_t smem_base = smem_u32(smem);

    const int t    = threadIdx.x;
    const int lane = t & 31;
    const int warp = t >> 5;
    const int g    = lane >> 2;
    const int tk   = lane & 3;
    const int wm   = (warp >> 2) * 64;
    const int wn   = (warp & 3) * 32;

    const int lrow0 = t >> 2;
    const int lch   = (t & 3) * 4;
    const int NKT   = K / BK;          // multiple of 4
    const int NTX   = N >> 7;
    const int NT    = NTX * (M >> 7);

    for (int tile = blockIdx.x; tile < NT; tile += gridDim.x) {
        const int rowBase = (tile / NTX) * 128;
        const int colBase = (tile % NTX) * 128;
        const float* Ag = A + (size_t)rowBase * K;
        const float* Bg = B + (size_t)colBase * K;

        float acc[16][4];
#pragma unroll
        for (int i = 0; i < 16; i++)
#pragma unroll
            for (int j = 0; j < 4; j++) acc[i][j] = 0.f;

        auto load_stage = [&](int s, int kt) {
            const int koff = kt * BK;
            const uint32_t As = smem_base + (uint32_t)(s * STAGE_F) * 4u;
            const uint32_t Bs = As + (uint32_t)ATILE * 4u;
#pragma unroll
            for (int rep = 0; rep < 2; rep++) {
                const int row = lrow0 + rep * 64;
                const uint32_t doff = (uint32_t)(row * KPITCH + lch) * 4u;
                cp_async16(As + doff, Ag + (size_t)row * K + koff + lch);
                cp_async16(Bs + doff, Bg + (size_t)row * K + koff + lch);
            }
        };

        load_stage(0, 0); cp_commit();
        load_stage(1, 1); cp_commit();
        load_stage(2, 2); cp_commit();

        for (int kt = 0; kt < NKT; kt++) {
            cp_wait<2>();
            __syncthreads();

            if (kt + 3 < NKT) load_stage((kt + 3) & 3, kt + 3);
            cp_commit();

            const float* As = smem + (kt & 3) * STAGE_F;
            const float* Bs = As + ATILE;

#pragma unroll
            for (int ks = 0; ks < 2; ks++) {
                const int k0 = ks * 8;
                unsigned a[4][4], b[4][2];
#pragma unroll
                for (int i = 0; i < 4; i++) {
                    const int m0 = wm + i * 16;
                    a[i][0] = __float_as_uint(As[(m0 + g)     * KPITCH + k0 + tk]);
                    a[i][1] = __float_as_uint(As[(m0 + g + 8) * KPITCH + k0 + tk]);
                    a[i][2] = __float_as_uint(As[(m0 + g)     * KPITCH + k0 + tk + 4]);
                    a[i][3] = __float_as_uint(As[(m0 + g + 8) * KPITCH + k0 + tk + 4]);
                }
#pragma unroll
                for (int j = 0; j < 4; j++) {
                    const int n0 = wn + j * 8;
                    b[j][0] = __float_as_uint(Bs[(n0 + g) * KPITCH + k0 + tk]);
                    b[j][1] = __float_as_uint(Bs[(n0 + g) * KPITCH + k0 + tk + 4]);
                }
#pragma unroll
                for (int i = 0; i < 4; i++)
#pragma unroll
                    for (int j = 0; j < 4; j++)
                        mma_tf32(acc[i * 4 + j], a[i], b[j]);
            }
        }

#pragma unroll
        for (int i = 0; i < 4; i++) {
#pragma unroll
            for (int j = 0; j < 4; j++) {
                const float* c = acc[i * 4 + j];
                const int row0 = rowBase + wm + i * 16 + g;
                const int col  = colBase + wn + j * 8 + tk * 2;
                *(float2*)(C + (size_t)row0 * N + col)       = make_float2(c[0], c[1]);
                *(float2*)(C + (size_t)(row0 + 8) * N + col) = make_float2(c[2], c[3]);
            }
        }
    }
}

// ================= GEMM2: A K-major from ygT, split-K=4, persistent =================
#define A2PITCH 136
#define A2TILE_B (BK * A2PITCH * 4)              // 8704 B
#define B2TILE_B (128 * KPITCH * 4)              // 10240 B
#define STAGE2_B (A2TILE_B + B2TILE_B)           // 18944 B
#define GSMEM2   (STAGES * STAGE2_B)             // 75776 B
#define SPLITK2  4
#define KLEN2    (DINNER / SPLITK2)              // 512, NKT=32 (mult of 4)

__global__ __launch_bounds__(256, 2) void gemm_tf32_At(const float* __restrict__ AT,
                                                       const float* __restrict__ B,
                                                       float* __restrict__ C0,
                                                       float* __restrict__ C1,
                                                       float* __restrict__ C2,
                                                       float* __restrict__ C3,
                                                       int N, int K) {
    extern __shared__ float smem[];
    const uint32_t smem_base = smem_u32(smem);

    const int t    = threadIdx.x;
    const int lane = t & 31;
    const int warp = t >> 5;
    const int g    = lane >> 2;
    const int tk   = lane & 3;
    const int wm   = (warp >> 2) * 64;
    const int wn   = (warp & 3) * 32;

    const int lrow0 = t >> 2;
    const int lch   = (t & 3) * 4;
    const int NKT   = KLEN2 / BK;
    const int NTX   = N >> 7;                    // 8
    const int TPZ   = NTX * (BL >> 7);           // 128 tiles per split
    const int NT    = TPZ * SPLITK2;             // 512

    for (int tile = blockIdx.x; tile < NT; tile += gridDim.x) {
        const int z   = tile / TPZ;
        const int r   = tile - z * TPZ;
        const int rowBase = (r / NTX) * 128;
        const int colBase = (r % NTX) * 128;
        const int kbase   = z * KLEN2;
        float* C = (z == 0) ? C0 : (z == 1) ? C1 : (z == 2) ? C2 : C3;

        const int b      = rowBase >> 10;
        const int t_base = rowBase & (SEQLEN - 1);
        const float* AgT = AT + ((size_t)(b * DINNER + kbase)) * SEQLEN + t_base;
        const float* Bg  = B + (size_t)colBase * K + kbase;

        float acc[16][4];
#pragma unroll
        for (int i = 0; i < 16; i++)
#pragma unroll
            for (int j = 0; j < 4; j++) acc[i][j] = 0.f;

        auto load_stage = [&](int s, int kt) {
            const int koff = kt * BK;
            const uint32_t As = smem_base + (uint32_t)(s * STAGE2_B);
            const uint32_t Bs = As + (uint32_t)A2TILE_B;
#pragma unroll
            for (int rep = 0; rep < 2; rep++) {
                const int c = t + rep * 256;
                const int k = c >> 5;
                const int off = (c & 31) * 4;
                cp_async16(As + (uint32_t)(k * A2PITCH + off) * 4u,
                           AgT + (size_t)(koff + k) * SEQLEN + off);
            }
#pragma unroll
            for (int rep = 0; rep < 2; rep++) {
                const int row = lrow0 + rep * 64;
                cp_async16(Bs + (uint32_t)(row * KPITCH + lch) * 4u,
                           Bg + (size_t)row * K + koff + lch);
            }
        };

        load_stage(0, 0); cp_commit();
        load_stage(1, 1); cp_commit();
        load_stage(2, 2); cp_commit();

        for (int kt = 0; kt < NKT; kt++) {
            cp_wait<2>();
            __syncthreads();

            if (kt + 3 < NKT) load_stage((kt + 3) & 3, kt + 3);
            cp_commit();

            const float* As = (const float*)((const char*)smem + (kt & 3) * STAGE2_B);
            const float* Bs = (const float*)((const char*)As + A2TILE_B);

#pragma unroll
            for (int ks = 0; ks < 2; ks++) {
                const int k0 = ks * 8;
                unsigned a[4][4], b[4][2];
#pragma unroll
                for (int i = 0; i < 4; i++) {
                    const int m0 = wm + i * 16;
                    a[i][0] = __float_as_uint(As[(k0 + tk)     * A2PITCH + m0 + g]);
                    a[i][1] = __float_as_uint(As[(k0 + tk)     * A2PITCH + m0 + g + 8]);
                    a[i][2] = __float_as_uint(As[(k0 + tk + 4) * A2PITCH + m0 + g]);
                    a[i][3] = __float_as_uint(As[(k0 + tk + 4) * A2PITCH + m0 + g + 8]);
                }
#pragma unroll
                for (int j = 0; j < 4; j++) {
                    const int n0 = wn + j * 8;
                    b[j][0] = __float_as_uint(Bs[(n0 + g) * KPITCH + k0 + tk]);
                    b[j][1] = __float_as_uint(Bs[(n0 + g) * KPITCH + k0 + tk + 4]);
                }
#pragma unroll
                for (int i = 0; i < 4; i++)
#pragma unroll
                    for (int j = 0; j < 4; j++)
                        mma_tf32(acc[i * 4 + j], a[i], b[j]);
            }
        }

#pragma unroll
        for (int i = 0; i < 4; i++) {
#pragma unroll
            for (int j = 0; j < 4; j++) {
                const float* c = acc[i * 4 + j];
                const int row0 = rowBase + wm + i * 16 + g;
                const int col  = colBase + wn + j * 8 + tk * 2;
                *(float2*)(C + (size_t)row0 * N + col)       = make_float2(c[0], c[1]);
                *(float2*)(C + (size_t)(row0 + 8) * N + col) = make_float2(c[2], c[3]);
            }
        }
    }
}

// ---------------- fused conv + SiLU -> xc, xcT; gate = silu(z) -> gateT ----------------
__global__ __launch_bounds__(256) void conv_prep(const float* __restrict__ conv_w,
                                                 const float* __restrict__ conv_b) {
    __shared__ float xt[36][33];
    __shared__ float tt[32][33];
    const int b  = blockIdx.z;
    const int l0 = blockIdx.x * 32;
    const int d0 = blockIdx.y * 32;
    const int tx = threadIdx.x & 31;
    const int ty = threadIdx.x >> 5;
    const int d  = d0 + tx;

    for (int r = ty; r < 35; r += 8) {
        const int l = l0 + r - 3;
        xt[r][tx] = (l >= 0) ? g_xz[(size_t)(b * SEQLEN + l) * (2 * DINNER) + d] : 0.f;
    }
    __syncthreads();

    const float w0 = conv_w[d * 4 + 0], w1 = conv_w[d * 4 + 1];
    const float w2 = conv_w[d * 4 + 2], w3 = conv_w[d * 4 + 3];
    const float cb = conv_b[d];
#pragma unroll
    for (int k4 = 0; k4 < 4; k4++) {
        const int lr = ty + k4 * 8;
        float acc = cb;
        acc = fmaf(w0, xt[lr][tx], acc);
        acc = fmaf(w1, xt[lr + 1][tx], acc);
        acc = fmaf(w2, xt[lr + 2][tx], acc);
        acc = fmaf(w3, xt[lr + 3][tx], acc);
        const float xc = acc / (1.f + __expf(-acc));
        g_xc[(size_t)(b * SEQLEN + l0 + lr) * DINNER + d] = xc;
        tt[lr][tx] = xc;
    }
    __syncthreads();
#pragma unroll
    for (int k4 = 0; k4 < 4; k4++) {
        const int dd = d0 + ty + k4 * 8;
        g_xcT[(size_t)(b * DINNER + dd) * SEQLEN + l0 + tx] = tt[tx][ty + k4 * 8];
    }
    __syncthreads();
#pragma unroll
    for (int k4 = 0; k4 < 4; k4++) {
        const int lr = ty + k4 * 8;
        const float z = g_xz[(size_t)(b * SEQLEN + l0 + lr) * (2 * DINNER) + DINNER + d];
        tt[lr][tx] = z / (1.f + __expf(-z));
    }
    __syncthreads();
#pragma unroll
    for (int k4 = 0; k4 < 4; k4++) {
        const int dd = d0 + ty + k4 * 8;
        g_gateT[(size_t)(b * DINNER + dd) * SEQLEN + l0 + tx] = tt[tx][ty + k4 * 8];
    }
}

// ---------------- x_proj rows 1..32: K-split 2, 8 rows/block, balanced ----------------
#define XR 8
#define XKH (DINNER / 2)                  // 1024
__global__ __launch_bounds__(256) void xproj_kernel(const float* __restrict__ W) {
    __shared__ float sx[XR * XKH];        // 32 KB
    const int bl0  = blockIdx.x * XR;
    const int koff = blockIdx.z * XKH;
    float* outp = blockIdx.z ? g_xp2 : g_xp;

    for (int i = threadIdx.x; i < XR * (XKH / 4); i += 256) {
        const int q = i >> 8;
        const int c = i & 255;
        ((float4*)sx)[i] = ((const float4*)(g_xc + (size_t)(bl0 + q) * DINNER + koff))[c];
    }
    __syncthreads();

    const int warp = threadIdx.x >> 5, lane = threadIdx.x & 31;
#pragma unroll
    for (int it = 0; it < 4; it++) {
        const int j = 1 + warp + it * 8;   // rows 1..32 (B and C)
        const float4* wr = (const float4*)(W + (size_t)j * DINNER + koff);
        float s[XR];
#pragma unroll
        for (int q = 0; q < XR; q++) s[q] = 0.f;
        for (int i = lane; i < XKH / 4; i += 32) {
            float4 w = __ldg(wr + i);
#pragma unroll
            for (int q = 0; q < XR; q++) {
                float4 xv = ((const float4*)(sx + q * XKH))[i];
                s[q] = fmaf(xv.x, w.x, fmaf(xv.y, w.y, fmaf(xv.z, w.z, fmaf(xv.w, w.w, s[q]))));
            }
        }
#pragma unroll
        for (int o = 16; o; o >>= 1)
#pragma unroll
            for (int q = 0; q < XR; q++)
                s[q] += __shfl_xor_sync(0xffffffffu, s[q], o);
        if (lane == 0) {
#pragma unroll
            for (int q = 0; q < XR; q++)
                outp[(size_t)(bl0 + q) * XPROJ_ROWS + j] = s[q];
        }
    }
}

// combine K-split partials for rows 1..32 only (row 0 written by dtrow_kernel)
__global__ __launch_bounds__(256) void xp_combine() {
    int i = blockIdx.x * 256 + threadIdx.x;
    if (i < BL * XPROJ_ROWS && (i % XPROJ_ROWS) != 0) g_xp[i] += g_xp2[i];
}

// ---------------- dt row (xp row 0): one warp per bl, full K ----------------
__global__ __launch_bounds__(256) void dtrow_kernel(const float* __restrict__ W) {
    const int wid  = blockIdx.x * 8 + (threadIdx.x >> 5);   // 0..2047
    const int lane = threadIdx.x & 31;
    const float4* xc = (const float4*)(g_xc + (size_t)wid * DINNER);
    const float4* w  = (const float4*)W;                    // row 0
    float s = 0.f;
    for (int i = lane; i < DINNER / 4; i += 32) {
        float4 a = xc[i];
        float4 b = __ldg(w + i);
        s = fmaf(a.x, b.x, fmaf(a.y, b.y, fmaf(a.z, b.z, fmaf(a.w, b.w, s))));
    }
#pragma unroll
    for (int o = 16; o; o >>= 1) s += __shfl_xor_sync(0xffffffffu, s, o);
    if (lane == 0) g_xp[(size_t)wid * XPROJ_ROWS] = s;
}

// ---------------- dtT = softplus(dtr*w + b), transposed ----------------
__global__ __launch_bounds__(256) void prep_dtT(const float* __restrict__ dtw,
                                                const float* __restrict__ dtb) {
    __shared__ float tile[32][33];
    const int b  = blockIdx.z;
    const int l0 = blockIdx.x * 32;
    const int d0 = blockIdx.y * 32;
    const int tx = threadIdx.x & 31;
    const int ty = threadIdx.x >> 5;
    const float w = dtw[d0 + tx], bb = dtb[d0 + tx];
#pragma unroll
    for (int k = 0; k < 4; k++) {
        const int l = l0 + ty + k * 8;
        const float dtr = g_xp[(size_t)(b * SEQLEN + l) * XPROJ_ROWS];
        const float xv = fmaf(dtr, w, bb);
        tile[ty + k * 8][tx] = fmaxf(xv, 0.f) + __logf(1.f + __expf(-fabsf(xv)));
    }
    __syncthreads();
#pragma unroll
    for (int k = 0; k < 4; k++) {
        const int dd = d0 + ty + k * 8;
        g_dtT[(size_t)(b * DINNER + dd) * SEQLEN + l0 + tx] = tile[tx][ty + k * 8];
    }
}

// ================= chunked selective scan (transposed streams) =================
#define SUNR 8

__device__ __forceinline__ void ld8(const float* p, int t0, float* v) {
    float4 a = __ldg((const float4*)(p + t0));
    float4 b = __ldg((const float4*)(p + t0 + 4));
    v[0] = a.x; v[1] = a.y; v[2] = a.z; v[3] = a.w;
    v[4] = b.x; v[5] = b.y; v[6] = b.z; v[7] = b.w;
}

__global__ __launch_bounds__(256) void scan_pass1(const float* __restrict__ A_log) {
    const int wg = blockIdx.x * 8 + (threadIdx.x >> 5);
    const int lane  = threadIdx.x & 31;
    const int group = lane >> 4;
    const int n     = lane & 15;
    const int pair  = wg / (NCHUNK - 1);
    const int chunk = wg - pair * (NCHUNK - 1);
    const int p2 = pair * 2;
    const int d  = (p2 & (DINNER - 1)) + group;
    const int b  = p2 >> 11;

    const float Acoef = -expf(A_log[d * NSTATE + n]);

    const float* xpb  = g_xp  + (size_t)b * SEQLEN * XPROJ_ROWS;
    const float* dtpT = g_dtT + (size_t)(b * DINNER + d) * SEQLEN;
    const float* xcpT = g_xcT + (size_t)(b * DINNER + d) * SEQLEN;

    float h = 0.f, S = 0.f;
    const int tb = chunk * LC;
    for (int t0 = tb; t0 < tb + LC; t0 += SUNR) {
        float dtv[SUNR], xcv[SUNR], Bv[SUNR];
        ld8(dtpT, t0, dtv);
        ld8(xcpT, t0, xcv);
#pragma unroll
        for (int u = 0; u < SUNR; u++)
            Bv[u] = __ldg(xpb + (size_t)(t0 + u) * XPROJ_ROWS + 1 + n);
#pragma unroll
        for (int u = 0; u < SUNR; u++) {
            const float dA = __expf(dtv[u] * Acoef);
            h = fmaf(dA, h, dtv[u] * xcv[u] * Bv[u]);
            S += dtv[u];
        }
    }
    g_Lh[(size_t)(pair * (NCHUNK - 1) + chunk) * 32 + lane] = h;
    if (n == 0)
        g_S[(size_t)(pair * (NCHUNK - 1) + chunk) * 2 + group] = S;
}

__global__ __launch_bounds__(256) void scan_pass2(const float* __restrict__ A_log) {
    const int gid  = blockIdx.x * 256 + threadIdx.x;
    const int pair = gid >> 5;
    const int lane = gid & 31;
    const int group = lane >> 4;
    const int n     = lane & 15;
    const int d = ((pair * 2) & (DINNER - 1)) + group;
    const float Acoef = -expf(A_log[d * NSTATE + n]);

    float hin = 0.f;
    g_Hin[(size_t)(pair * NCHUNK) * 32 + lane] = 0.f;
#pragma unroll
    for (int c = 0; c < NCHUNK - 1; c++) {
        const float S = g_S[(size_t)(pair * (NCHUNK - 1) + c) * 2 + group];
        const float L = g_Lh[(size_t)(pair * (NCHUNK - 1) + c) * 32 + lane];
        hin = fmaf(__expf(Acoef * S), hin, L);
        g_Hin[(size_t)(pair * NCHUNK + c + 1) * 32 + lane] = hin;
    }
}

__global__ __launch_bounds__(256) void scan_pass3(const float* __restrict__ A_log,
                                                  const float* __restrict__ D_param) {
    const int wg = blockIdx.x * 8 + (threadIdx.x >> 5);
    const int lane  = threadIdx.x & 31;
    const int group = lane >> 4;
    const int n     = lane & 15;
    const int pair  = wg >> 4;              // NCHUNK = 16
    const int chunk = wg & (NCHUNK - 1);
    const int p2 = pair * 2;
    const int d  = (p2 & (DINNER - 1)) + group;
    const int b  = p2 >> 11;

    const float Acoef = -expf(A_log[d * NSTATE + n]);
    const float Dp    = D_param[d];

    const float* xpb  = g_xp    + (size_t)b * SEQLEN * XPROJ_ROWS;
    const float* dtpT = g_dtT   + (size_t)(b * DINNER + d) * SEQLEN;
    const float* xcpT = g_xcT   + (size_t)(b * DINNER + d) * SEQLEN;
    const float* gpT  = g_gateT + (size_t)(b * DINNER + d) * SEQLEN;
    float*       ygpT = g_ygT   + (size_t)(b * DINNER + d) * SEQLEN;

    float h = g_Hin[(size_t)(pair * NCHUNK + chunk) * 32 + lane];
    const int tb = chunk * LC;
    for (int t0 = tb; t0 < tb + LC; t0 += SUNR) {
        float dtv[SUNR], xcv[SUNR], gv[SUNR], Bv[SUNR], Cv[SUNR];
        ld8(dtpT, t0, dtv);
        ld8(xcpT, t0, xcv);
        ld8(gpT,  t0, gv);
#pragma unroll
        for (int u = 0; u < SUNR; u++) {
            const float* xpr = xpb + (size_t)(t0 + u) * XPROJ_ROWS;
            Bv[u] = __ldg(xpr + 1 + n);
            Cv[u] = __ldg(xpr + 1 + NSTATE + n);
        }
        float y[SUNR];
#pragma unroll
        for (int u = 0; u < SUNR; u++) {
            const float dA = __expf(dtv[u] * Acoef);
            h = fmaf(dA, h, dtv[u] * xcv[u] * Bv[u]);
            y[u] = h * Cv[u];
        }
#pragma unroll
        for (int u = 0; u < SUNR; u++) {
            y[u] += __shfl_xor_sync(0xffffffffu, y[u], 8);
            y[u] += __shfl_xor_sync(0xffffffffu, y[u], 4);
            y[u] += __shfl_xor_sync(0xffffffffu, y[u], 2);
            y[u] += __shfl_xor_sync(0xffffffffu, y[u], 1);
        }
        if (n == 0) {
            float o[SUNR];
#pragma unroll
            for (int u = 0; u < SUNR; u++) {
                const float yy = fmaf(xcv[u], Dp, y[u]);
                o[u] = __uint_as_float(f2tf32(yy * gv[u]));
            }
            *(float4*)(ygpT + t0)     = make_float4(o[0], o[1], o[2], o[3]);
            *(float4*)(ygpT + t0 + 4) = make_float4(o[4], o[5], o[6], o[7]);
        }
    }
}

// ---------------- launch ----------------
extern "C" void kernel_launch(void* const* d_in, const int* in_sizes, int n_in,
                              void* d_out, int out_size) {
    const float* x          = (const float*)d_in[0];
    const float* in_proj_w  = (const float*)d_in[1];
    const float* conv_w     = (const float*)d_in[2];
    const float* conv_b     = (const float*)d_in[3];
    const float* x_proj_w   = (const float*)d_in[4];
    const float* dt_proj_w  = (const float*)d_in[5];
    const float* dt_proj_b  = (const float*)d_in[6];
    const float* A_log      = (const float*)d_in[7];
    const float* D_param    = (const float*)d_in[8];
    const float* out_proj_w = (const float*)d_in[9];
    float* out = (float*)d_out;

    float *xz_p = nullptr, *xr_p = nullptr, *w1_p = nullptr, *w2_p = nullptr,
          *xc_p = nullptr, *pk_p = nullptr, *ygT_p = nullptr;
    cudaGetSymbolAddress((void**)&xz_p, g_xz);
    cudaGetSymbolAddress((void**)&xr_p, g_xr);
    cudaGetSymbolAddress((void**)&w1_p, g_w1r);
    cudaGetSymbolAddress((void**)&w2_p, g_w2r);
    cudaGetSymbolAddress((void**)&xc_p, g_xc);
    cudaGetSymbolAddress((void**)&pk_p, g_pk);
    cudaGetSymbolAddress((void**)&ygT_p, g_ygT);

    static int attr_set = 0;
    if (!attr_set) {
        cudaFuncSetAttribute(gemm_tf32_pipe, cudaFuncAttributeMaxDynamicSharedMemorySize, GSMEM);
        cudaFuncSetAttribute(gemm_tf32_At, cudaFuncAttributeMaxDynamicSharedMemorySize, GSMEM2);
        attr_set = 1;
    }

    // 0) RNA-round all GEMM inputs
    {
        int total = XN4 + W1N4 + W2N4;
        rna_round_all<<<(total + 255) / 256, 256>>>(x, in_proj_w, out_proj_w);
    }

    // 1) xz = x @ in_proj_w^T  (persistent)
    gemm_tf32_pipe<<<PGRID, 256, GSMEM>>>(xr_p, w1_p, xz_p, BL, 2 * DINNER, DMODEL);

    // 2) fused conv+silu -> xc, xcT; gate -> gateT
    conv_prep<<<dim3(SEQLEN / 32, DINNER / 32, BATCH), 256>>>(conv_w, conv_b);

    // 3) xp rows 1..32 (K-split 2 + combine); row 0 via dtrow
    xproj_kernel<<<dim3(BL / XR, 1, 2), 256>>>(x_proj_w);
    dtrow_kernel<<<BL / 8, 256>>>(x_proj_w);
    xp_combine<<<(BL * XPROJ_ROWS + 255) / 256, 256>>>();

    // 4) dtT (softplus, transposed)
    prep_dtT<<<dim3(SEQLEN / 32, DINNER / 32, BATCH), 256>>>(dt_proj_w, dt_proj_b);

    // 5) chunked selective scan -> ygT
    scan_pass1<<<(NPAIR * (NCHUNK - 1)) / 8, 256>>>(A_log);
    scan_pass2<<<(NPAIR * 32) / 256, 256>>>(A_log);
    scan_pass3<<<(NPAIR * NCHUNK) / 8, 256>>>(A_log, D_param);

    // 6) out = ygT^T @ out_proj_w^T, split-K=4, persistent
    gemm_tf32_At<<<PGRID, 256, GSMEM2>>>(
        ygT_p, w2_p, pk_p, pk_p + (size_t)BL * DMODEL, xc_p, xr_p, DMODEL, DINNER);
    {
        int n4 = (BL * DMODEL) / 4;
        add4_kernel<<<(n4 + 255) / 256, 256>>>(pk_p, pk_p + (size_t)BL * DMODEL,
                                               xc_p, xr_p, out, n4);
    }
}

// round 14
// speedup vs baseline: 1.0026x; 1.0026x over previous
#include <cuda_runtime.h>
#include <math.h>
#include <stdint.h>

#define BATCH   2
#define SEQLEN  1024
#define DMODEL  1024
#define DINNER  2048
#define NSTATE  16
#define BL      (BATCH*SEQLEN)      // 2048 rows
#define XPROJ_ROWS 33               // 1 dt + 16 B + 16 C
#define NCHUNK  16
#define LC      (SEQLEN/NCHUNK)     // 64
#define NPAIR   (BATCH*DINNER/2)    // 2048 warp-pairs
#define PGRID   296                 // persistent GEMM grid (148 SMs x 2 CTAs)

// ---------------- scratch (no allocs allowed) ----------------
__device__ float g_xz[(size_t)BL * 2 * DINNER];   // [bl][4096]
__device__ float g_xc[(size_t)BL * DINNER];       // conv out; later split-K partial 2
__device__ float g_xp[(size_t)BL * XPROJ_ROWS];
__device__ float g_xp2[(size_t)BL * XPROJ_ROWS];  // xproj K-split partial
__device__ float g_pk[(size_t)BL * DINNER];       // split-K partials 0,1
// transposed [b][d][t] scan streams
__device__ float g_dtT[(size_t)BL * DINNER];
__device__ float g_xcT[(size_t)BL * DINNER];
__device__ float g_gateT[(size_t)BL * DINNER];
__device__ float g_ygT[(size_t)BL * DINNER];
// TF32-rounded copies of GEMM inputs (g_xr later split-K partial 3)
__device__ float g_xr[(size_t)BL * DMODEL];
__device__ float g_w1r[(size_t)(2*DINNER) * DMODEL];
__device__ float g_w2r[(size_t)DMODEL * DINNER];
// chunked-scan scratch
__device__ float g_S [(size_t)NPAIR * (NCHUNK-1) * 2];
__device__ float g_Lh[(size_t)NPAIR * (NCHUNK-1) * 32];
__device__ float g_Hin[(size_t)NPAIR * NCHUNK * 32];

__device__ __forceinline__ unsigned f2tf32(float x) {
    unsigned r;
    asm("cvt.rna.tf32.f32 %0, %1;" : "=r"(r) : "f"(x));
    return r;
}

// ---------------- fused RNA pre-rounding ----------------
#define XN4   ((BL * DMODEL) / 4)
#define W1N4  ((2 * DINNER * DMODEL) / 4)
#define W2N4  ((DMODEL * DINNER) / 4)
__global__ __launch_bounds__(256) void rna_round_all(const float* __restrict__ x,
                                                     const float* __restrict__ w1,
                                                     const float* __restrict__ w2) {
    int i = blockIdx.x * 256 + threadIdx.x;
    const float4* src;
    float4* dst;
    int off;
    if (i < XN4)              { src = (const float4*)x;  dst = (float4*)g_xr;  off = i; }
    else if (i < XN4 + W1N4)  { src = (const float4*)w1; dst = (float4*)g_w1r; off = i - XN4; }
    else if (i < XN4 + W1N4 + W2N4) { src = (const float4*)w2; dst = (float4*)g_w2r; off = i - XN4 - W1N4; }
    else return;
    float4 v = src[off];
    v.x = __uint_as_float(f2tf32(v.x));
    v.y = __uint_as_float(f2tf32(v.y));
    v.z = __uint_as_float(f2tf32(v.z));
    v.w = __uint_as_float(f2tf32(v.w));
    dst[off] = v;
}

// ---------------- add pass for split-K=4 ----------------
__global__ __launch_bounds__(256) void add4_kernel(const float* __restrict__ p0,
                                                   const float* __restrict__ p1,
                                                   const float* __restrict__ p2,
                                                   const float* __restrict__ p3,
                                                   float* __restrict__ out, int n4) {
    int i = blockIdx.x * 256 + threadIdx.x;
    if (i >= n4) return;
    float4 a = ((const float4*)p0)[i];
    float4 b = ((const float4*)p1)[i];
    float4 c = ((const float4*)p2)[i];
    float4 d = ((const float4*)p3)[i];
    ((float4*)out)[i] = make_float4((a.x + b.x) + (c.x + d.x),
                                    (a.y + b.y) + (c.y + d.y),
                                    (a.z + b.z) + (c.z + d.z),
                                    (a.w + b.w) + (c.w + d.w));
}

// ================= common GEMM helpers =================
#define BK      16
#define KPITCH  20
#define ATILE   (128 * KPITCH)
#define STAGE_F (2 * ATILE)
#define STAGES  4
#define GSMEM   (STAGES * STAGE_F * 4)   // 81920 B

__device__ __forceinline__ uint32_t smem_u32(const void* p) {
    uint32_t a;
    asm("{ .reg .u64 t; cvta.to.shared.u64 t, %1; cvt.u32.u64 %0, t; }" : "=r"(a) : "l"(p));
    return a;
}
__device__ __forceinline__ void cp_async16(uint32_t dst, const void* src) {
    asm volatile("cp.async.cg.shared.global [%0], [%1], 16;" :: "r"(dst), "l"(src));
}
__device__ __forceinline__ void cp_commit() {
    asm volatile("cp.async.commit_group;");
}
template <int N>
__device__ __forceinline__ void cp_wait() {
    asm volatile("cp.async.wait_group %0;" :: "n"(N));
}
__device__ __forceinline__ void mma_tf32(float* c, const unsigned* a, const unsigned* b) {
    asm volatile(
        "mma.sync.aligned.m16n8k8.row.col.f32.tf32.tf32.f32 "
        "{%0,%1,%2,%3}, {%4,%5,%6,%7}, {%8,%9}, {%0,%1,%2,%3};\n"
        : "+f"(c[0]), "+f"(c[1]), "+f"(c[2]), "+f"(c[3])
        : "r"(a[0]), "r"(a[1]), "r"(a[2]), "r"(a[3]), "r"(b[0]), "r"(b[1]));
}

// ================= GEMM1 (A row-major), persistent tile loop =================
__global__ __launch_bounds__(256, 2) void gemm_tf32_pipe(const float* __restrict__ A,
                                                         const float* __restrict__ B,
                                                         float* __restrict__ C,
                                                         int M, int N, int K) {
    extern __shared__ float smem[];
    const uint32_t smem_base = smem_u32(smem);

    const int t    = threadIdx.x;
    const int lane = t & 31;
    const int warp = t >> 5;
    const int g    = lane >> 2;
    const int tk   = lane & 3;
    const int wm   = (warp >> 2) * 64;
    const int wn   = (warp & 3) * 32;

    const int lrow0 = t >> 2;
    const int lch   = (t & 3) * 4;
    const int NKT   = K / BK;          // multiple of 4
    const int NTX   = N >> 7;
    const int NT    = NTX * (M >> 7);

    for (int tile = blockIdx.x; tile < NT; tile += gridDim.x) {
        const int rowBase = (tile / NTX) * 128;
        const int colBase = (tile % NTX) * 128;
        const float* Ag = A + (size_t)rowBase * K;
        const float* Bg = B + (size_t)colBase * K;

        float acc[16][4];
#pragma unroll
        for (int i = 0; i < 16; i++)
#pragma unroll
            for (int j = 0; j < 4; j++) acc[i][j] = 0.f;

        auto load_stage = [&](int s, int kt) {
            const int koff = kt * BK;
            const uint32_t As = smem_base + (uint32_t)(s * STAGE_F) * 4u;
            const uint32_t Bs = As + (uint32_t)ATILE * 4u;
#pragma unroll
            for (int rep = 0; rep < 2; rep++) {
                const int row = lrow0 + rep * 64;
                const uint32_t doff = (uint32_t)(row * KPITCH + lch) * 4u;
                cp_async16(As + doff, Ag + (size_t)row * K + koff + lch);
                cp_async16(Bs + doff, Bg + (size_t)row * K + koff + lch);
            }
        };

        load_stage(0, 0); cp_commit();
        load_stage(1, 1); cp_commit();
        load_stage(2, 2); cp_commit();

        for (int kt = 0; kt < NKT; kt++) {
            cp_wait<2>();
            __syncthreads();

            if (kt + 3 < NKT) load_stage((kt + 3) & 3, kt + 3);
            cp_commit();

            const float* As = smem + (kt & 3) * STAGE_F;
            const float* Bs = As + ATILE;

#pragma unroll
            for (int ks = 0; ks < 2; ks++) {
                const int k0 = ks * 8;
                unsigned a[4][4], b[4][2];
#pragma unroll
                for (int i = 0; i < 4; i++) {
                    const int m0 = wm + i * 16;
                    a[i][0] = __float_as_uint(As[(m0 + g)     * KPITCH + k0 + tk]);
                    a[i][1] = __float_as_uint(As[(m0 + g + 8) * KPITCH + k0 + tk]);
                    a[i][2] = __float_as_uint(As[(m0 + g)     * KPITCH + k0 + tk + 4]);
                    a[i][3] = __float_as_uint(As[(m0 + g + 8) * KPITCH + k0 + tk + 4]);
                }
#pragma unroll
                for (int j = 0; j < 4; j++) {
                    const int n0 = wn + j * 8;
                    b[j][0] = __float_as_uint(Bs[(n0 + g) * KPITCH + k0 + tk]);
                    b[j][1] = __float_as_uint(Bs[(n0 + g) * KPITCH + k0 + tk + 4]);
                }
#pragma unroll
                for (int i = 0; i < 4; i++)
#pragma unroll
                    for (int j = 0; j < 4; j++)
                        mma_tf32(acc[i * 4 + j], a[i], b[j]);
            }
        }

#pragma unroll
        for (int i = 0; i < 4; i++) {
#pragma unroll
            for (int j = 0; j < 4; j++) {
                const float* c = acc[i * 4 + j];
                const int row0 = rowBase + wm + i * 16 + g;
                const int col  = colBase + wn + j * 8 + tk * 2;
                *(float2*)(C + (size_t)row0 * N + col)       = make_float2(c[0], c[1]);
                *(float2*)(C + (size_t)(row0 + 8) * N + col) = make_float2(c[2], c[3]);
            }
        }
    }
}

// ================= GEMM2: A K-major from ygT, split-K=4, persistent =================
#define A2PITCH 136
#define A2TILE_B (BK * A2PITCH * 4)              // 8704 B
#define B2TILE_B (128 * KPITCH * 4)              // 10240 B
#define STAGE2_B (A2TILE_B + B2TILE_B)           // 18944 B
#define GSMEM2   (STAGES * STAGE2_B)             // 75776 B
#define SPLITK2  4
#define KLEN2    (DINNER / SPLITK2)              // 512, NKT=32 (mult of 4)

__global__ __launch_bounds__(256, 2) void gemm_tf32_At(const float* __restrict__ AT,
                                                       const float* __restrict__ B,
                                                       float* __restrict__ C0,
                                                       float* __restrict__ C1,
                                                       float* __restrict__ C2,
                                                       float* __restrict__ C3,
                                                       int N, int K) {
    extern __shared__ float smem[];
    const uint32_t smem_base = smem_u32(smem);

    const int t    = threadIdx.x;
    const int lane = t & 31;
    const int warp = t >> 5;
    const int g    = lane >> 2;
    const int tk   = lane & 3;
    const int wm   = (warp >> 2) * 64;
    const int wn   = (warp & 3) * 32;

    const int lrow0 = t >> 2;
    const int lch   = (t & 3) * 4;
    const int NKT   = KLEN2 / BK;
    const int NTX   = N >> 7;                    // 8
    const int TPZ   = NTX * (BL >> 7);           // 128 tiles per split
    const int NT    = TPZ * SPLITK2;             // 512

    for (int tile = blockIdx.x; tile < NT; tile += gridDim.x) {
        const int z   = tile / TPZ;
        const int r   = tile - z * TPZ;
        const int rowBase = (r / NTX) * 128;
        const int colBase = (r % NTX) * 128;
        const int kbase   = z * KLEN2;
        float* C = (z == 0) ? C0 : (z == 1) ? C1 : (z == 2) ? C2 : C3;

        const int b      = rowBase >> 10;
        const int t_base = rowBase & (SEQLEN - 1);
        const float* AgT = AT + ((size_t)(b * DINNER + kbase)) * SEQLEN + t_base;
        const float* Bg  = B + (size_t)colBase * K + kbase;

        float acc[16][4];
#pragma unroll
        for (int i = 0; i < 16; i++)
#pragma unroll
            for (int j = 0; j < 4; j++) acc[i][j] = 0.f;

        auto load_stage = [&](int s, int kt) {
            const int koff = kt * BK;
            const uint32_t As = smem_base + (uint32_t)(s * STAGE2_B);
            const uint32_t Bs = As + (uint32_t)A2TILE_B;
#pragma unroll
            for (int rep = 0; rep < 2; rep++) {
                const int c = t + rep * 256;
                const int k = c >> 5;
                const int off = (c & 31) * 4;
                cp_async16(As + (uint32_t)(k * A2PITCH + off) * 4u,
                           AgT + (size_t)(koff + k) * SEQLEN + off);
            }
#pragma unroll
            for (int rep = 0; rep < 2; rep++) {
                const int row = lrow0 + rep * 64;
                cp_async16(Bs + (uint32_t)(row * KPITCH + lch) * 4u,
                           Bg + (size_t)row * K + koff + lch);
            }
        };

        load_stage(0, 0); cp_commit();
        load_stage(1, 1); cp_commit();
        load_stage(2, 2); cp_commit();

        for (int kt = 0; kt < NKT; kt++) {
            cp_wait<2>();
            __syncthreads();

            if (kt + 3 < NKT) load_stage((kt + 3) & 3, kt + 3);
            cp_commit();

            const float* As = (const float*)((const char*)smem + (kt & 3) * STAGE2_B);
            const float* Bs = (const float*)((const char*)As + A2TILE_B);

#pragma unroll
            for (int ks = 0; ks < 2; ks++) {
                const int k0 = ks * 8;
                unsigned a[4][4], b[4][2];
#pragma unroll
                for (int i = 0; i < 4; i++) {
                    const int m0 = wm + i * 16;
                    a[i][0] = __float_as_uint(As[(k0 + tk)     * A2PITCH + m0 + g]);
                    a[i][1] = __float_as_uint(As[(k0 + tk)     * A2PITCH + m0 + g + 8]);
                    a[i][2] = __float_as_uint(As[(k0 + tk + 4) * A2PITCH + m0 + g]);
                    a[i][3] = __float_as_uint(As[(k0 + tk + 4) * A2PITCH + m0 + g + 8]);
                }
#pragma unroll
                for (int j = 0; j < 4; j++) {
                    const int n0 = wn + j * 8;
                    b[j][0] = __float_as_uint(Bs[(n0 + g) * KPITCH + k0 + tk]);
                    b[j][1] = __float_as_uint(Bs[(n0 + g) * KPITCH + k0 + tk + 4]);
                }
#pragma unroll
                for (int i = 0; i < 4; i++)
#pragma unroll
                    for (int j = 0; j < 4; j++)
                        mma_tf32(acc[i * 4 + j], a[i], b[j]);
            }
        }

#pragma unroll
        for (int i = 0; i < 4; i++) {
#pragma unroll
            for (int j = 0; j < 4; j++) {
                const float* c = acc[i * 4 + j];
                const int row0 = rowBase + wm + i * 16 + g;
                const int col  = colBase + wn + j * 8 + tk * 2;
                *(float2*)(C + (size_t)row0 * N + col)       = make_float2(c[0], c[1]);
                *(float2*)(C + (size_t)(row0 + 8) * N + col) = make_float2(c[2], c[3]);
            }
        }
    }
}

// ---------------- fused conv + SiLU -> xc, xcT; gate = silu(z) -> gateT ----------------
__global__ __launch_bounds__(256) void conv_prep(const float* __restrict__ conv_w,
                                                 const float* __restrict__ conv_b) {
    __shared__ float xt[36][33];
    __shared__ float tt[32][33];
    const int b  = blockIdx.z;
    const int l0 = blockIdx.x * 32;
    const int d0 = blockIdx.y * 32;
    const int tx = threadIdx.x & 31;
    const int ty = threadIdx.x >> 5;
    const int d  = d0 + tx;

    for (int r = ty; r < 35; r += 8) {
        const int l = l0 + r - 3;
        xt[r][tx] = (l >= 0) ? g_xz[(size_t)(b * SEQLEN + l) * (2 * DINNER) + d] : 0.f;
    }
    __syncthreads();

    const float w0 = conv_w[d * 4 + 0], w1 = conv_w[d * 4 + 1];
    const float w2 = conv_w[d * 4 + 2], w3 = conv_w[d * 4 + 3];
    const float cb = conv_b[d];
#pragma unroll
    for (int k4 = 0; k4 < 4; k4++) {
        const int lr = ty + k4 * 8;
        float acc = cb;
        acc = fmaf(w0, xt[lr][tx], acc);
        acc = fmaf(w1, xt[lr + 1][tx], acc);
        acc = fmaf(w2, xt[lr + 2][tx], acc);
        acc = fmaf(w3, xt[lr + 3][tx], acc);
        const float xc = acc / (1.f + __expf(-acc));
        g_xc[(size_t)(b * SEQLEN + l0 + lr) * DINNER + d] = xc;
        tt[lr][tx] = xc;
    }
    __syncthreads();
#pragma unroll
    for (int k4 = 0; k4 < 4; k4++) {
        const int dd = d0 + ty + k4 * 8;
        g_xcT[(size_t)(b * DINNER + dd) * SEQLEN + l0 + tx] = tt[tx][ty + k4 * 8];
    }
    __syncthreads();
#pragma unroll
    for (int k4 = 0; k4 < 4; k4++) {
        const int lr = ty + k4 * 8;
        const float z = g_xz[(size_t)(b * SEQLEN + l0 + lr) * (2 * DINNER) + DINNER + d];
        tt[lr][tx] = z / (1.f + __expf(-z));
    }
    __syncthreads();
#pragma unroll
    for (int k4 = 0; k4 < 4; k4++) {
        const int dd = d0 + ty + k4 * 8;
        g_gateT[(size_t)(b * DINNER + dd) * SEQLEN + l0 + tx] = tt[tx][ty + k4 * 8];
    }
}

// ---------------- x_proj rows 1..32: K-split 2, 8 rows/block, balanced ----------------
#define XR 8
#define XKH (DINNER / 2)                  // 1024
__global__ __launch_bounds__(256) void xproj_kernel(const float* __restrict__ W) {
    __shared__ float sx[XR * XKH];        // 32 KB
    const int bl0  = blockIdx.x * XR;
    const int koff = blockIdx.z * XKH;
    float* outp = blockIdx.z ? g_xp2 : g_xp;

    for (int i = threadIdx.x; i < XR * (XKH / 4); i += 256) {
        const int q = i >> 8;
        const int c = i & 255;
        ((float4*)sx)[i] = ((const float4*)(g_xc + (size_t)(bl0 + q) * DINNER + koff))[c];
    }
    __syncthreads();

    const int warp = threadIdx.x >> 5, lane = threadIdx.x & 31;
#pragma unroll
    for (int it = 0; it < 4; it++) {
        const int j = 1 + warp + it * 8;   // rows 1..32 (B and C)
        const float4* wr = (const float4*)(W + (size_t)j * DINNER + koff);
        float s[XR];
#pragma unroll
        for (int q = 0; q < XR; q++) s[q] = 0.f;
        for (int i = lane; i < XKH / 4; i += 32) {
            float4 w = __ldg(wr + i);
#pragma unroll
            for (int q = 0; q < XR; q++) {
                float4 xv = ((const float4*)(sx + q * XKH))[i];
                s[q] = fmaf(xv.x, w.x, fmaf(xv.y, w.y, fmaf(xv.z, w.z, fmaf(xv.w, w.w, s[q]))));
            }
        }
#pragma unroll
        for (int o = 16; o; o >>= 1)
#pragma unroll
            for (int q = 0; q < XR; q++)
                s[q] += __shfl_xor_sync(0xffffffffu, s[q], o);
        if (lane == 0) {
#pragma unroll
            for (int q = 0; q < XR; q++)
                outp[(size_t)(bl0 + q) * XPROJ_ROWS + j] = s[q];
        }
    }
}

// combine K-split partials for rows 1..32 only (row 0 written by dtrow_kernel)
__global__ __launch_bounds__(256) void xp_combine() {
    int i = blockIdx.x * 256 + threadIdx.x;
    if (i < BL * XPROJ_ROWS && (i % XPROJ_ROWS) != 0) g_xp[i] += g_xp2[i];
}

// ---------------- dt row (xp row 0): one warp per bl, full K ----------------
__global__ __launch_bounds__(256) void dtrow_kernel(const float* __restrict__ W) {
    const int wid  = blockIdx.x * 8 + (threadIdx.x >> 5);   // 0..2047
    const int lane = threadIdx.x & 31;
    const float4* xc = (const float4*)(g_xc + (size_t)wid * DINNER);
    const float4* w  = (const float4*)W;                    // row 0
    float s = 0.f;
    for (int i = lane; i < DINNER / 4; i += 32) {
        float4 a = xc[i];
        float4 b = __ldg(w + i);
        s = fmaf(a.x, b.x, fmaf(a.y, b.y, fmaf(a.z, b.z, fmaf(a.w, b.w, s))));
    }
#pragma unroll
    for (int o = 16; o; o >>= 1) s += __shfl_xor_sync(0xffffffffu, s, o);
    if (lane == 0) g_xp[(size_t)wid * XPROJ_ROWS] = s;
}

// ---------------- dtT = softplus(dtr*w + b), transposed ----------------
__global__ __launch_bounds__(256) void prep_dtT(const float* __restrict__ dtw,
                                                const float* __restrict__ dtb) {
    __shared__ float tile[32][33];
    const int b  = blockIdx.z;
    const int l0 = blockIdx.x * 32;
    const int d0 = blockIdx.y * 32;
    const int tx = threadIdx.x & 31;
    const int ty = threadIdx.x >> 5;
    const float w = dtw[d0 + tx], bb = dtb[d0 + tx];
#pragma unroll
    for (int k = 0; k < 4; k++) {
        const int l = l0 + ty + k * 8;
        const float dtr = g_xp[(size_t)(b * SEQLEN + l) * XPROJ_ROWS];
        const float xv = fmaf(dtr, w, bb);
        tile[ty + k * 8][tx] = fmaxf(xv, 0.f) + __logf(1.f + __expf(-fabsf(xv)));
    }
    __syncthreads();
#pragma unroll
    for (int k = 0; k < 4; k++) {
        const int dd = d0 + ty + k * 8;
        g_dtT[(size_t)(b * DINNER + dd) * SEQLEN + l0 + tx] = tile[tx][ty + k * 8];
    }
}

// ================= chunked selective scan (transposed streams) =================
#define SUNR 8

__device__ __forceinline__ void ld8(const float* p, int t0, float* v) {
    float4 a = __ldg((const float4*)(p + t0));
    float4 b = __ldg((const float4*)(p + t0 + 4));
    v[0] = a.x; v[1] = a.y; v[2] = a.z; v[3] = a.w;
    v[4] = b.x; v[5] = b.y; v[6] = b.z; v[7] = b.w;
}

__global__ __launch_bounds__(256) void scan_pass1(const float* __restrict__ A_log) {
    const int wg = blockIdx.x * 8 + (threadIdx.x >> 5);
    const int lane  = threadIdx.x & 31;
    const int group = lane >> 4;
    const int n     = lane & 15;
    const int pair  = wg / (NCHUNK - 1);
    const int chunk = wg - pair * (NCHUNK - 1);
    const int p2 = pair * 2;
    const int d  = (p2 & (DINNER - 1)) + group;
    const int b  = p2 >> 11;

    const float Acoef = -expf(A_log[d * NSTATE + n]);

    const float* xpb  = g_xp  + (size_t)b * SEQLEN * XPROJ_ROWS;
    const float* dtpT = g_dtT + (size_t)(b * DINNER + d) * SEQLEN;
    const float* xcpT = g_xcT + (size_t)(b * DINNER + d) * SEQLEN;

    float h = 0.f, S = 0.f;
    const int tb = chunk * LC;
    for (int t0 = tb; t0 < tb + LC; t0 += SUNR) {
        float dtv[SUNR], xcv[SUNR], Bv[SUNR];
        ld8(dtpT, t0, dtv);
        ld8(xcpT, t0, xcv);
#pragma unroll
        for (int u = 0; u < SUNR; u++)
            Bv[u] = __ldg(xpb + (size_t)(t0 + u) * XPROJ_ROWS + 1 + n);
#pragma unroll
        for (int u = 0; u < SUNR; u++) {
            const float dA = __expf(dtv[u] * Acoef);
            h = fmaf(dA, h, dtv[u] * xcv[u] * Bv[u]);
            S += dtv[u];
        }
    }
    g_Lh[(size_t)(pair * (NCHUNK - 1) + chunk) * 32 + lane] = h;
    if (n == 0)
        g_S[(size_t)(pair * (NCHUNK - 1) + chunk) * 2 + group] = S;
}

__global__ __launch_bounds__(256) void scan_pass2(const float* __restrict__ A_log) {
    const int gid  = blockIdx.x * 256 + threadIdx.x;
    const int pair = gid >> 5;
    const int lane = gid & 31;
    const int group = lane >> 4;
    const int n     = lane & 15;
    const int d = ((pair * 2) & (DINNER - 1)) + group;
    const float Acoef = -expf(A_log[d * NSTATE + n]);

    float hin = 0.f;
    g_Hin[(size_t)(pair * NCHUNK) * 32 + lane] = 0.f;
#pragma unroll
    for (int c = 0; c < NCHUNK - 1; c++) {
        const float S = g_S[(size_t)(pair * (NCHUNK - 1) + c) * 2 + group];
        const float L = g_Lh[(size_t)(pair * (NCHUNK - 1) + c) * 32 + lane];
        hin = fmaf(__expf(Acoef * S), hin, L);
        g_Hin[(size_t)(pair * NCHUNK + c + 1) * 32 + lane] = hin;
    }
}

__global__ __launch_bounds__(256) void scan_pass3(const float* __restrict__ A_log,
                                                  const float* __restrict__ D_param) {
    const int wg = blockIdx.x * 8 + (threadIdx.x >> 5);
    const int lane  = threadIdx.x & 31;
    const int group = lane >> 4;
    const int n     = lane & 15;
    const int pair  = wg >> 4;              // NCHUNK = 16
    const int chunk = wg & (NCHUNK - 1);
    const int p2 = pair * 2;
    const int d  = (p2 & (DINNER - 1)) + group;
    const int b  = p2 >> 11;

    const float Acoef = -expf(A_log[d * NSTATE + n]);
    const float Dp    = D_param[d];

    const float* xpb  = g_xp    + (size_t)b * SEQLEN * XPROJ_ROWS;
    const float* dtpT = g_dtT   + (size_t)(b * DINNER + d) * SEQLEN;
    const float* xcpT = g_xcT   + (size_t)(b * DINNER + d) * SEQLEN;
    const float* gpT  = g_gateT + (size_t)(b * DINNER + d) * SEQLEN;
    float*       ygpT = g_ygT   + (size_t)(b * DINNER + d) * SEQLEN;

    float h = g_Hin[(size_t)(pair * NCHUNK + chunk) * 32 + lane];
    const int tb = chunk * LC;
    for (int t0 = tb; t0 < tb + LC; t0 += SUNR) {
        float dtv[SUNR], xcv[SUNR], gv[SUNR], Bv[SUNR], Cv[SUNR];
        ld8(dtpT, t0, dtv);
        ld8(xcpT, t0, xcv);
        ld8(gpT,  t0, gv);
#pragma unroll
        for (int u = 0; u < SUNR; u++) {
            const float* xpr = xpb + (size_t)(t0 + u) * XPROJ_ROWS;
            Bv[u] = __ldg(xpr + 1 + n);
            Cv[u] = __ldg(xpr + 1 + NSTATE + n);
        }
        float y[SUNR];
#pragma unroll
        for (int u = 0; u < SUNR; u++) {
            const float dA = __expf(dtv[u] * Acoef);
            h = fmaf(dA, h, dtv[u] * xcv[u] * Bv[u]);
            y[u] = h * Cv[u];
        }
#pragma unroll
        for (int u = 0; u < SUNR; u++) {
            y[u] += __shfl_xor_sync(0xffffffffu, y[u], 8);
            y[u] += __shfl_xor_sync(0xffffffffu, y[u], 4);
            y[u] += __shfl_xor_sync(0xffffffffu, y[u], 2);
            y[u] += __shfl_xor_sync(0xffffffffu, y[u], 1);
        }
        if (n == 0) {
            float o[SUNR];
#pragma unroll
            for (int u = 0; u < SUNR; u++) {
                const float yy = fmaf(xcv[u], Dp, y[u]);
                o[u] = __uint_as_float(f2tf32(yy * gv[u]));
            }
            *(float4*)(ygpT + t0)     = make_float4(o[0], o[1], o[2], o[3]);
            *(float4*)(ygpT + t0 + 4) = make_float4(o[4], o[5], o[6], o[7]);
        }
    }
}

// ---------------- launch ----------------
extern "C" void kernel_launch(void* const* d_in, const int* in_sizes, int n_in,
                              void* d_out, int out_size) {
    const float* x          = (const float*)d_in[0];
    const float* in_proj_w  = (const float*)d_in[1];
    const float* conv_w     = (const float*)d_in[2];
    const float* conv_b     = (const float*)d_in[3];
    const float* x_proj_w   = (const float*)d_in[4];
    const float* dt_proj_w  = (const float*)d_in[5];
    const float* dt_proj_b  = (const float*)d_in[6];
    const float* A_log      = (const float*)d_in[7];
    const float* D_param    = (const float*)d_in[8];
    const float* out_proj_w = (const float*)d_in[9];
    float* out = (float*)d_out;

    float *xz_p = nullptr, *xr_p = nullptr, *w1_p = nullptr, *w2_p = nullptr,
          *xc_p = nullptr, *pk_p = nullptr, *ygT_p = nullptr;
    cudaGetSymbolAddress((void**)&xz_p, g_xz);
    cudaGetSymbolAddress((void**)&xr_p, g_xr);
    cudaGetSymbolAddress((void**)&w1_p, g_w1r);
    cudaGetSymbolAddress((void**)&w2_p, g_w2r);
    cudaGetSymbolAddress((void**)&xc_p, g_xc);
    cudaGetSymbolAddress((void**)&pk_p, g_pk);
    cudaGetSymbolAddress((void**)&ygT_p, g_ygT);

    static int attr_set = 0;
    if (!attr_set) {
        cudaFuncSetAttribute(gemm_tf32_pipe, cudaFuncAttributeMaxDynamicSharedMemorySize, GSMEM);
        cudaFuncSetAttribute(gemm_tf32_At, cudaFuncAttributeMaxDynamicSharedMemorySize, GSMEM2);
        attr_set = 1;
    }

    // 0) RNA-round all GEMM inputs
    {
        int total = XN4 + W1N4 + W2N4;
        rna_round_all<<<(total + 255) / 256, 256>>>(x, in_proj_w, out_proj_w);
    }

    // 1) xz = x @ in_proj_w^T  (persistent)
    gemm_tf32_pipe<<<PGRID, 256, GSMEM>>>(xr_p, w1_p, xz_p, BL, 2 * DINNER, DMODEL);

    // 2) fused conv+silu -> xc, xcT; gate -> gateT
    conv_prep<<<dim3(SEQLEN / 32, DINNER / 32, BATCH), 256>>>(conv_w, conv_b);

    // 3) xp rows 1..32 (K-split 2 + combine); row 0 via dtrow
    xproj_kernel<<<dim3(BL / XR, 1, 2), 256>>>(x_proj_w);
    dtrow_kernel<<<BL / 8, 256>>>(x_proj_w);
    xp_combine<<<(BL * XPROJ_ROWS + 255) / 256, 256>>>();

    // 4) dtT (softplus, transposed)
    prep_dtT<<<dim3(SEQLEN / 32, DINNER / 32, BATCH), 256>>>(dt_proj_w, dt_proj_b);

    // 5) chunked selective scan -> ygT
    scan_pass1<<<(NPAIR * (NCHUNK - 1)) / 8, 256>>>(A_log);
    scan_pass2<<<(NPAIR * 32) / 256, 256>>>(A_log);
    scan_pass3<<<(NPAIR * NCHUNK) / 8, 256>>>(A_log, D_param);

    // 6) out = ygT^T @ out_proj_w^T, split-K=4, persistent
    gemm_tf32_At<<<PGRID, 256, GSMEM2>>>(
        ygT_p, w2_p, pk_p, pk_p + (size_t)BL * DMODEL, xc_p, xr_p, DMODEL, DINNER);
    {
        int n4 = (BL * DMODEL) / 4;
        add4_kernel<<<(n4 + 255) / 256, 256>>>(pk_p, pk_p + (size_t)BL * DMODEL,
                                               xc_p, xr_p, out, n4);
    }
}

// round 15
// speedup vs baseline: 1.0760x; 1.0732x over previous
#include <cuda_runtime.h>
#include <math.h>
#include <stdint.h>

#define BATCH   2
#define SEQLEN  1024
#define DMODEL  1024
#define DINNER  2048
#define NSTATE  16
#define BL      (BATCH*SEQLEN)      // 2048 rows
#define XPROJ_ROWS 33               // 1 dt + 16 B + 16 C
#define NCHUNK  8
#define LC      (SEQLEN/NCHUNK)     // 128
#define NPAIR   (BATCH*DINNER/2)    // 2048 warp-pairs

// ---------------- scratch (no allocs allowed) ----------------
__device__ float g_xz[(size_t)BL * 2 * DINNER];   // [bl][4096]
__device__ float g_xc[(size_t)BL * DINNER];       // conv out; later split-K partial 2
__device__ float g_xp[(size_t)BL * XPROJ_ROWS];
__device__ float g_xp2[(size_t)BL * XPROJ_ROWS];  // xproj K-split partial
__device__ float g_pk[(size_t)BL * DINNER];       // split-K partials 0,1
// transposed [b][d][t] scan streams
__device__ float g_dtT[(size_t)BL * DINNER];
__device__ float g_xcT[(size_t)BL * DINNER];
__device__ float g_gateT[(size_t)BL * DINNER];
__device__ float g_ygT[(size_t)BL * DINNER];
// TF32-rounded copies of GEMM inputs (g_xr later split-K partial 3)
__device__ float g_xr[(size_t)BL * DMODEL];
__device__ float g_w1r[(size_t)(2*DINNER) * DMODEL];
__device__ float g_w2r[(size_t)DMODEL * DINNER];
// chunked-scan scratch
__device__ float g_S [(size_t)NPAIR * (NCHUNK-1) * 2];
__device__ float g_Lh[(size_t)NPAIR * (NCHUNK-1) * 32];
__device__ float g_Hin[(size_t)NPAIR * NCHUNK * 32];

__device__ __forceinline__ unsigned f2tf32(float x) {
    unsigned r;
    asm("cvt.rna.tf32.f32 %0, %1;" : "=r"(r) : "f"(x));
    return r;
}

// ---------------- fused RNA pre-rounding ----------------
#define XN4   ((BL * DMODEL) / 4)
#define W1N4  ((2 * DINNER * DMODEL) / 4)
#define W2N4  ((DMODEL * DINNER) / 4)
__global__ __launch_bounds__(256) void rna_round_all(const float* __restrict__ x,
                                                     const float* __restrict__ w1,
                                                     const float* __restrict__ w2) {
    int i = blockIdx.x * 256 + threadIdx.x;
    const float4* src;
    float4* dst;
    int off;
    if (i < XN4)              { src = (const float4*)x;  dst = (float4*)g_xr;  off = i; }
    else if (i < XN4 + W1N4)  { src = (const float4*)w1; dst = (float4*)g_w1r; off = i - XN4; }
    else if (i < XN4 + W1N4 + W2N4) { src = (const float4*)w2; dst = (float4*)g_w2r; off = i - XN4 - W1N4; }
    else return;
    float4 v = src[off];
    v.x = __uint_as_float(f2tf32(v.x));
    v.y = __uint_as_float(f2tf32(v.y));
    v.z = __uint_as_float(f2tf32(v.z));
    v.w = __uint_as_float(f2tf32(v.w));
    dst[off] = v;
}

// ---------------- add pass for split-K=4 ----------------
__global__ __launch_bounds__(256) void add4_kernel(const float* __restrict__ p0,
                                                   const float* __restrict__ p1,
                                                   const float* __restrict__ p2,
                                                   const float* __restrict__ p3,
                                                   float* __restrict__ out, int n4) {
    int i = blockIdx.x * 256 + threadIdx.x;
    if (i >= n4) return;
    float4 a = ((const float4*)p0)[i];
    float4 b = ((const float4*)p1)[i];
    float4 c = ((const float4*)p2)[i];
    float4 d = ((const float4*)p3)[i];
    ((float4*)out)[i] = make_float4((a.x + b.x) + (c.x + d.x),
                                    (a.y + b.y) + (c.y + d.y),
                                    (a.z + b.z) + (c.z + d.z),
                                    (a.w + b.w) + (c.w + d.w));
}

// ================= common GEMM helpers =================
#define BK      16
#define KPITCH  20
#define ATILE   (128 * KPITCH)
#define STAGE_F (2 * ATILE)
#define STAGES  4
#define GSMEM   (STAGES * STAGE_F * 4)   // 81920 B

__device__ __forceinline__ uint32_t smem_u32(const void* p) {
    uint32_t a;
    asm("{ .reg .u64 t; cvta.to.shared.u64 t, %1; cvt.u32.u64 %0, t; }" : "=r"(a) : "l"(p));
    return a;
}
__device__ __forceinline__ void cp_async16(uint32_t dst, const void* src) {
    asm volatile("cp.async.cg.shared.global [%0], [%1], 16;" :: "r"(dst), "l"(src));
}
__device__ __forceinline__ void cp_commit() {
    asm volatile("cp.async.commit_group;");
}
template <int N>
__device__ __forceinline__ void cp_wait() {
    asm volatile("cp.async.wait_group %0;" :: "n"(N));
}
__device__ __forceinline__ void mma_tf32(float* c, const unsigned* a, const unsigned* b) {
    asm volatile(
        "mma.sync.aligned.m16n8k8.row.col.f32.tf32.tf32.f32 "
        "{%0,%1,%2,%3}, {%4,%5,%6,%7}, {%8,%9}, {%0,%1,%2,%3};\n"
        : "+f"(c[0]), "+f"(c[1]), "+f"(c[2]), "+f"(c[3])
        : "r"(a[0]), "r"(a[1]), "r"(a[2]), "r"(a[3]), "r"(b[0]), "r"(b[1]));
}

// ================= GEMM1 (A row-major): 128 threads, 64x64 warp tiles =================
__global__ __launch_bounds__(128, 2) void gemm_tf32_pipe(const float* __restrict__ A,
                                                         const float* __restrict__ B,
                                                         float* __restrict__ C,
                                                         int M, int N, int K) {
    extern __shared__ float smem[];
    const uint32_t smem_base = smem_u32(smem);

    const int t    = threadIdx.x;
    const int lane = t & 31;
    const int warp = t >> 5;           // 0..3
    const int g    = lane >> 2;
    const int tk   = lane & 3;
    const int wm   = (warp >> 1) * 64;
    const int wn   = (warp & 1) * 64;

    const int rowBase = blockIdx.y * 128;
    const int colBase = blockIdx.x * 128;
    const float* Ag = A + (size_t)rowBase * K;
    const float* Bg = B + (size_t)colBase * K;

    const int lrow0 = t >> 2;          // 0..31
    const int lch   = (t & 3) * 4;
    const int NKT   = K / BK;

    float acc[32][4];
#pragma unroll
    for (int i = 0; i < 32; i++)
#pragma unroll
        for (int j = 0; j < 4; j++) acc[i][j] = 0.f;

    auto load_stage = [&](int s, int kt) {
        const int koff = kt * BK;
        const uint32_t As = smem_base + (uint32_t)(s * STAGE_F) * 4u;
        const uint32_t Bs = As + (uint32_t)ATILE * 4u;
#pragma unroll
        for (int rep = 0; rep < 4; rep++) {
            const int row = lrow0 + rep * 32;
            const uint32_t doff = (uint32_t)(row * KPITCH + lch) * 4u;
            cp_async16(As + doff, Ag + (size_t)row * K + koff + lch);
            cp_async16(Bs + doff, Bg + (size_t)row * K + koff + lch);
        }
    };

    load_stage(0, 0); cp_commit();
    if (NKT > 1) load_stage(1, 1);
    cp_commit();
    if (NKT > 2) load_stage(2, 2);
    cp_commit();

    for (int kt = 0; kt < NKT; kt++) {
        cp_wait<2>();
        __syncthreads();

        if (kt + 3 < NKT) load_stage((kt + 3) & 3, kt + 3);
        cp_commit();

        const float* As = smem + (kt & 3) * STAGE_F;
        const float* Bs = As + ATILE;

#pragma unroll
        for (int ks = 0; ks < 2; ks++) {
            const int k0 = ks * 8;
            unsigned a[4][4], b[8][2];
#pragma unroll
            for (int i = 0; i < 4; i++) {
                const int m0 = wm + i * 16;
                a[i][0] = __float_as_uint(As[(m0 + g)     * KPITCH + k0 + tk]);
                a[i][1] = __float_as_uint(As[(m0 + g + 8) * KPITCH + k0 + tk]);
                a[i][2] = __float_as_uint(As[(m0 + g)     * KPITCH + k0 + tk + 4]);
                a[i][3] = __float_as_uint(As[(m0 + g + 8) * KPITCH + k0 + tk + 4]);
            }
#pragma unroll
            for (int j = 0; j < 8; j++) {
                const int n0 = wn + j * 8;
                b[j][0] = __float_as_uint(Bs[(n0 + g) * KPITCH + k0 + tk]);
                b[j][1] = __float_as_uint(Bs[(n0 + g) * KPITCH + k0 + tk + 4]);
            }
#pragma unroll
            for (int i = 0; i < 4; i++)
#pragma unroll
                for (int j = 0; j < 8; j++)
                    mma_tf32(acc[i * 8 + j], a[i], b[j]);
        }
        __syncthreads();
    }

#pragma unroll
    for (int i = 0; i < 4; i++) {
#pragma unroll
        for (int j = 0; j < 8; j++) {
            const float* c = acc[i * 8 + j];
            const int row0 = rowBase + wm + i * 16 + g;
            const int col  = colBase + wn + j * 8 + tk * 2;
            *(float2*)(C + (size_t)row0 * N + col)       = make_float2(c[0], c[1]);
            *(float2*)(C + (size_t)(row0 + 8) * N + col) = make_float2(c[2], c[3]);
        }
    }
}

// ================= GEMM2: A K-major from ygT, split-K=4, 128 threads =================
#define A2PITCH 136
#define A2TILE_B (BK * A2PITCH * 4)              // 8704 B
#define B2TILE_B (128 * KPITCH * 4)              // 10240 B
#define STAGE2_B (A2TILE_B + B2TILE_B)           // 18944 B
#define GSMEM2   (STAGES * STAGE2_B)             // 75776 B

__global__ __launch_bounds__(128, 2) void gemm_tf32_At(const float* __restrict__ AT,
                                                       const float* __restrict__ B,
                                                       float* __restrict__ C0,
                                                       float* __restrict__ C1,
                                                       float* __restrict__ C2,
                                                       float* __restrict__ C3,
                                                       int N, int K, int klen) {
    extern __shared__ float smem[];
    const uint32_t smem_base = smem_u32(smem);

    const int t    = threadIdx.x;
    const int lane = t & 31;
    const int warp = t >> 5;
    const int g    = lane >> 2;
    const int tk   = lane & 3;
    const int wm   = (warp >> 1) * 64;
    const int wn   = (warp & 1) * 64;

    const int rowBase = blockIdx.y * 128;
    const int colBase = blockIdx.x * 128;
    const int kbase   = blockIdx.z * klen;
    float* C = (blockIdx.z == 0) ? C0 : (blockIdx.z == 1) ? C1 : (blockIdx.z == 2) ? C2 : C3;

    const int b      = rowBase >> 10;
    const int t_base = rowBase & (SEQLEN - 1);
    const float* AgT = AT + ((size_t)(b * DINNER + kbase)) * SEQLEN + t_base;
    const float* Bg  = B + (size_t)colBase * K + kbase;

    const int lrow0 = t >> 2;
    const int lch   = (t & 3) * 4;
    const int NKT   = klen / BK;

    float acc[32][4];
#pragma unroll
    for (int i = 0; i < 32; i++)
#pragma unroll
        for (int j = 0; j < 4; j++) acc[i][j] = 0.f;

    auto load_stage = [&](int s, int kt) {
        const int koff = kt * BK;
        const uint32_t As = smem_base + (uint32_t)(s * STAGE2_B);
        const uint32_t Bs = As + (uint32_t)A2TILE_B;
        // A: 512 16B chunks (16 k-rows x 32 chunks of 4 t) over 128 threads
#pragma unroll
        for (int rep = 0; rep < 4; rep++) {
            const int c = t + rep * 128;
            const int k = c >> 5;
            const int off = (c & 31) * 4;
            cp_async16(As + (uint32_t)(k * A2PITCH + off) * 4u,
                       AgT + (size_t)(koff + k) * SEQLEN + off);
        }
        // B
#pragma unroll
        for (int rep = 0; rep < 4; rep++) {
            const int row = lrow0 + rep * 32;
            cp_async16(Bs + (uint32_t)(row * KPITCH + lch) * 4u,
                       Bg + (size_t)row * K + koff + lch);
        }
    };

    load_stage(0, 0); cp_commit();
    if (NKT > 1) load_stage(1, 1);
    cp_commit();
    if (NKT > 2) load_stage(2, 2);
    cp_commit();

    for (int kt = 0; kt < NKT; kt++) {
        cp_wait<2>();
        __syncthreads();

        if (kt + 3 < NKT) load_stage((kt + 3) & 3, kt + 3);
        cp_commit();

        const float* As = (const float*)((const char*)smem + (kt & 3) * STAGE2_B);
        const float* Bs = (const float*)((const char*)As + A2TILE_B);

#pragma unroll
        for (int ks = 0; ks < 2; ks++) {
            const int k0 = ks * 8;
            unsigned a[4][4], b[8][2];
#pragma unroll
            for (int i = 0; i < 4; i++) {
                const int m0 = wm + i * 16;
                a[i][0] = __float_as_uint(As[(k0 + tk)     * A2PITCH + m0 + g]);
                a[i][1] = __float_as_uint(As[(k0 + tk)     * A2PITCH + m0 + g + 8]);
                a[i][2] = __float_as_uint(As[(k0 + tk + 4) * A2PITCH + m0 + g]);
                a[i][3] = __float_as_uint(As[(k0 + tk + 4) * A2PITCH + m0 + g + 8]);
            }
#pragma unroll
            for (int j = 0; j < 8; j++) {
                const int n0 = wn + j * 8;
                b[j][0] = __float_as_uint(Bs[(n0 + g) * KPITCH + k0 + tk]);
                b[j][1] = __float_as_uint(Bs[(n0 + g) * KPITCH + k0 + tk + 4]);
            }
#pragma unroll
            for (int i = 0; i < 4; i++)
#pragma unroll
                for (int j = 0; j < 8; j++)
                    mma_tf32(acc[i * 8 + j], a[i], b[j]);
        }
        __syncthreads();
    }

#pragma unroll
    for (int i = 0; i < 4; i++) {
#pragma unroll
        for (int j = 0; j < 8; j++) {
            const float* c = acc[i * 8 + j];
            const int row0 = rowBase + wm + i * 16 + g;
            const int col  = colBase + wn + j * 8 + tk * 2;
            *(float2*)(C + (size_t)row0 * N + col)       = make_float2(c[0], c[1]);
            *(float2*)(C + (size_t)(row0 + 8) * N + col) = make_float2(c[2], c[3]);
        }
    }
}

// ---------------- fused conv + SiLU -> xc, xcT; gate = silu(z) -> gateT ----------------
__global__ __launch_bounds__(256) void conv_prep(const float* __restrict__ conv_w,
                                                 const float* __restrict__ conv_b) {
    __shared__ float xt[36][33];
    __shared__ float tt[32][33];
    const int b  = blockIdx.z;
    const int l0 = blockIdx.x * 32;
    const int d0 = blockIdx.y * 32;
    const int tx = threadIdx.x & 31;
    const int ty = threadIdx.x >> 5;
    const int d  = d0 + tx;

    for (int r = ty; r < 35; r += 8) {
        const int l = l0 + r - 3;
        xt[r][tx] = (l >= 0) ? g_xz[(size_t)(b * SEQLEN + l) * (2 * DINNER) + d] : 0.f;
    }
    __syncthreads();

    const float w0 = conv_w[d * 4 + 0], w1 = conv_w[d * 4 + 1];
    const float w2 = conv_w[d * 4 + 2], w3 = conv_w[d * 4 + 3];
    const float cb = conv_b[d];
#pragma unroll
    for (int k4 = 0; k4 < 4; k4++) {
        const int lr = ty + k4 * 8;
        float acc = cb;
        acc = fmaf(w0, xt[lr][tx], acc);
        acc = fmaf(w1, xt[lr + 1][tx], acc);
        acc = fmaf(w2, xt[lr + 2][tx], acc);
        acc = fmaf(w3, xt[lr + 3][tx], acc);
        const float xc = acc / (1.f + __expf(-acc));
        g_xc[(size_t)(b * SEQLEN + l0 + lr) * DINNER + d] = xc;
        tt[lr][tx] = xc;
    }
    __syncthreads();
#pragma unroll
    for (int k4 = 0; k4 < 4; k4++) {
        const int dd = d0 + ty + k4 * 8;
        g_xcT[(size_t)(b * DINNER + dd) * SEQLEN + l0 + tx] = tt[tx][ty + k4 * 8];
    }
    __syncthreads();
#pragma unroll
    for (int k4 = 0; k4 < 4; k4++) {
        const int lr = ty + k4 * 8;
        const float z = g_xz[(size_t)(b * SEQLEN + l0 + lr) * (2 * DINNER) + DINNER + d];
        tt[lr][tx] = z / (1.f + __expf(-z));
    }
    __syncthreads();
#pragma unroll
    for (int k4 = 0; k4 < 4; k4++) {
        const int dd = d0 + ty + k4 * 8;
        g_gateT[(size_t)(b * DINNER + dd) * SEQLEN + l0 + tx] = tt[tx][ty + k4 * 8];
    }
}

// ---------------- x_proj: K-split 2, 8 rows/block, 32 KB smem ----------------
#define XR 8
#define XKH (DINNER / 2)                  // 1024
__global__ __launch_bounds__(256) void xproj_kernel(const float* __restrict__ W) {
    __shared__ float sx[XR * XKH];        // 32 KB
    const int bl0  = blockIdx.x * XR;
    const int koff = blockIdx.z * XKH;
    float* outp = blockIdx.z ? g_xp2 : g_xp;

    for (int i = threadIdx.x; i < XR * (XKH / 4); i += 256) {
        const int q = i >> 8;
        const int c = i & 255;
        ((float4*)sx)[i] = ((const float4*)(g_xc + (size_t)(bl0 + q) * DINNER + koff))[c];
    }
    __syncthreads();

    const int warp = threadIdx.x >> 5, lane = threadIdx.x & 31;
    for (int j = warp; j < XPROJ_ROWS; j += 8) {
        const float4* wr = (const float4*)(W + (size_t)j * DINNER + koff);
        float s[XR];
#pragma unroll
        for (int q = 0; q < XR; q++) s[q] = 0.f;
        for (int i = lane; i < XKH / 4; i += 32) {
            float4 w = __ldg(wr + i);
#pragma unroll
            for (int q = 0; q < XR; q++) {
                float4 xv = ((const float4*)(sx + q * XKH))[i];
                s[q] = fmaf(xv.x, w.x, fmaf(xv.y, w.y, fmaf(xv.z, w.z, fmaf(xv.w, w.w, s[q]))));
            }
        }
#pragma unroll
        for (int o = 16; o; o >>= 1)
#pragma unroll
            for (int q = 0; q < XR; q++)
                s[q] += __shfl_xor_sync(0xffffffffu, s[q], o);
        if (lane == 0) {
#pragma unroll
            for (int q = 0; q < XR; q++)
                outp[(size_t)(bl0 + q) * XPROJ_ROWS + j] = s[q];
        }
    }
}

__global__ __launch_bounds__(256) void xp_combine() {
    int i = blockIdx.x * 256 + threadIdx.x;
    if (i < BL * XPROJ_ROWS) g_xp[i] += g_xp2[i];
}

// ---------------- dtT = softplus(dtr*w + b), transposed ----------------
__global__ __launch_bounds__(256) void prep_dtT(const float* __restrict__ dtw,
                                                const float* __restrict__ dtb) {
    __shared__ float tile[32][33];
    const int b  = blockIdx.z;
    const int l0 = blockIdx.x * 32;
    const int d0 = blockIdx.y * 32;
    const int tx = threadIdx.x & 31;
    const int ty = threadIdx.x >> 5;
    const float w = dtw[d0 + tx], bb = dtb[d0 + tx];
#pragma unroll
    for (int k = 0; k < 4; k++) {
        const int l = l0 + ty + k * 8;
        const float dtr = g_xp[(size_t)(b * SEQLEN + l) * XPROJ_ROWS];
        const float xv = fmaf(dtr, w, bb);
        tile[ty + k * 8][tx] = fmaxf(xv, 0.f) + __logf(1.f + __expf(-fabsf(xv)));
    }
    __syncthreads();
#pragma unroll
    for (int k = 0; k < 4; k++) {
        const int dd = d0 + ty + k * 8;
        g_dtT[(size_t)(b * DINNER + dd) * SEQLEN + l0 + tx] = tile[tx][ty + k * 8];
    }
}

// ================= chunked selective scan (transposed streams) =================
#define SUNR 8

__device__ __forceinline__ void ld8(const float* p, int t0, float* v) {
    float4 a = __ldg((const float4*)(p + t0));
    float4 b = __ldg((const float4*)(p + t0 + 4));
    v[0] = a.x; v[1] = a.y; v[2] = a.z; v[3] = a.w;
    v[4] = b.x; v[5] = b.y; v[6] = b.z; v[7] = b.w;
}

__global__ __launch_bounds__(256) void scan_pass1(const float* __restrict__ A_log) {
    const int wg = blockIdx.x * 8 + (threadIdx.x >> 5);
    const int lane  = threadIdx.x & 31;
    const int group = lane >> 4;
    const int n     = lane & 15;
    const int pair  = wg / (NCHUNK - 1);
    const int chunk = wg - pair * (NCHUNK - 1);
    const int p2 = pair * 2;
    const int d  = (p2 & (DINNER - 1)) + group;
    const int b  = p2 >> 11;

    const float Acoef = -expf(A_log[d * NSTATE + n]);

    const float* xpb  = g_xp  + (size_t)b * SEQLEN * XPROJ_ROWS;
    const float* dtpT = g_dtT + (size_t)(b * DINNER + d) * SEQLEN;
    const float* xcpT = g_xcT + (size_t)(b * DINNER + d) * SEQLEN;

    float h = 0.f, S = 0.f;
    const int tb = chunk * LC;
    for (int t0 = tb; t0 < tb + LC; t0 += SUNR) {
        float dtv[SUNR], xcv[SUNR], Bv[SUNR];
        ld8(dtpT, t0, dtv);
        ld8(xcpT, t0, xcv);
#pragma unroll
        for (int u = 0; u < SUNR; u++)
            Bv[u] = __ldg(xpb + (size_t)(t0 + u) * XPROJ_ROWS + 1 + n);
#pragma unroll
        for (int u = 0; u < SUNR; u++) {
            const float dA = __expf(dtv[u] * Acoef);
            h = fmaf(dA, h, dtv[u] * xcv[u] * Bv[u]);
            S += dtv[u];
        }
    }
    g_Lh[(size_t)(pair * (NCHUNK - 1) + chunk) * 32 + lane] = h;
    if (n == 0)
        g_S[(size_t)(pair * (NCHUNK - 1) + chunk) * 2 + group] = S;
}

__global__ __launch_bounds__(256) void scan_pass2(const float* __restrict__ A_log) {
    const int gid  = blockIdx.x * 256 + threadIdx.x;
    const int pair = gid >> 5;
    const int lane = gid & 31;
    const int group = lane >> 4;
    const int n     = lane & 15;
    const int d = ((pair * 2) & (DINNER - 1)) + group;
    const float Acoef = -expf(A_log[d * NSTATE + n]);

    float hin = 0.f;
    g_Hin[(size_t)(pair * NCHUNK) * 32 + lane] = 0.f;
#pragma unroll
    for (int c = 0; c < NCHUNK - 1; c++) {
        const float S = g_S[(size_t)(pair * (NCHUNK - 1) + c) * 2 + group];
        const float L = g_Lh[(size_t)(pair * (NCHUNK - 1) + c) * 32 + lane];
        hin = fmaf(__expf(Acoef * S), hin, L);
        g_Hin[(size_t)(pair * NCHUNK + c + 1) * 32 + lane] = hin;
    }
}

__global__ __launch_bounds__(256) void scan_pass3(const float* __restrict__ A_log,
                                                  const float* __restrict__ D_param) {
    const int wg = blockIdx.x * 8 + (threadIdx.x >> 5);
    const int lane  = threadIdx.x & 31;
    const int group = lane >> 4;
    const int n     = lane & 15;
    const int pair  = wg >> 3;
    const int chunk = wg & 7;
    const int p2 = pair * 2;
    const int d  = (p2 & (DINNER - 1)) + group;
    const int b  = p2 >> 11;

    const float Acoef = -expf(A_log[d * NSTATE + n]);
    const float Dp    = D_param[d];

    const float* xpb  = g_xp    + (size_t)b * SEQLEN * XPROJ_ROWS;
    const float* dtpT = g_dtT   + (size_t)(b * DINNER + d) * SEQLEN;
    const float* xcpT = g_xcT   + (size_t)(b * DINNER + d) * SEQLEN;
    const float* gpT  = g_gateT + (size_t)(b * DINNER + d) * SEQLEN;
    float*       ygpT = g_ygT   + (size_t)(b * DINNER + d) * SEQLEN;

    float h = g_Hin[(size_t)(pair * NCHUNK + chunk) * 32 + lane];
    const int tb = chunk * LC;
    for (int t0 = tb; t0 < tb + LC; t0 += SUNR) {
        float dtv[SUNR], xcv[SUNR], gv[SUNR], Bv[SUNR], Cv[SUNR];
        ld8(dtpT, t0, dtv);
        ld8(xcpT, t0, xcv);
        ld8(gpT,  t0, gv);
#pragma unroll
        for (int u = 0; u < SUNR; u++) {
            const float* xpr = xpb + (size_t)(t0 + u) * XPROJ_ROWS;
            Bv[u] = __ldg(xpr + 1 + n);
            Cv[u] = __ldg(xpr + 1 + NSTATE + n);
        }
        float y[SUNR];
#pragma unroll
        for (int u = 0; u < SUNR; u++) {
            const float dA = __expf(dtv[u] * Acoef);
            h = fmaf(dA, h, dtv[u] * xcv[u] * Bv[u]);
            y[u] = h * Cv[u];
        }
#pragma unroll
        for (int u = 0; u < SUNR; u++) {
            y[u] += __shfl_xor_sync(0xffffffffu, y[u], 8);
            y[u] += __shfl_xor_sync(0xffffffffu, y[u], 4);
            y[u] += __shfl_xor_sync(0xffffffffu, y[u], 2);
            y[u] += __shfl_xor_sync(0xffffffffu, y[u], 1);
        }
        if (n == 0) {
            float o[SUNR];
#pragma unroll
            for (int u = 0; u < SUNR; u++) {
                const float yy = fmaf(xcv[u], Dp, y[u]);
                o[u] = __uint_as_float(f2tf32(yy * gv[u]));
            }
            *(float4*)(ygpT + t0)     = make_float4(o[0], o[1], o[2], o[3]);
            *(float4*)(ygpT + t0 + 4) = make_float4(o[4], o[5], o[6], o[7]);
        }
    }
}

// ---------------- launch ----------------
extern "C" void kernel_launch(void* const* d_in, const int* in_sizes, int n_in,
                              void* d_out, int out_size) {
    const float* x          = (const float*)d_in[0];
    const float* in_proj_w  = (const float*)d_in[1];
    const float* conv_w     = (const float*)d_in[2];
    const float* conv_b     = (const float*)d_in[3];
    const float* x_proj_w   = (const float*)d_in[4];
    const float* dt_proj_w  = (const float*)d_in[5];
    const float* dt_proj_b  = (const float*)d_in[6];
    const float* A_log      = (const float*)d_in[7];
    const float* D_param    = (const float*)d_in[8];
    const float* out_proj_w = (const float*)d_in[9];
    float* out = (float*)d_out;

    float *xz_p = nullptr, *xr_p = nullptr, *w1_p = nullptr, *w2_p = nullptr,
          *xc_p = nullptr, *pk_p = nullptr, *ygT_p = nullptr;
    cudaGetSymbolAddress((void**)&xz_p, g_xz);
    cudaGetSymbolAddress((void**)&xr_p, g_xr);
    cudaGetSymbolAddress((void**)&w1_p, g_w1r);
    cudaGetSymbolAddress((void**)&w2_p, g_w2r);
    cudaGetSymbolAddress((void**)&xc_p, g_xc);
    cudaGetSymbolAddress((void**)&pk_p, g_pk);
    cudaGetSymbolAddress((void**)&ygT_p, g_ygT);

    static int attr_set = 0;
    if (!attr_set) {
        cudaFuncSetAttribute(gemm_tf32_pipe, cudaFuncAttributeMaxDynamicSharedMemorySize, GSMEM);
        cudaFuncSetAttribute(gemm_tf32_At, cudaFuncAttributeMaxDynamicSharedMemorySize, GSMEM2);
        attr_set = 1;
    }

    // 0) RNA-round all GEMM inputs
    {
        int total = XN4 + W1N4 + W2N4;
        rna_round_all<<<(total + 255) / 256, 256>>>(x, in_proj_w, out_proj_w);
    }

    // 1) xz = x @ in_proj_w^T
    gemm_tf32_pipe<<<dim3((2 * DINNER) / 128, BL / 128), 128, GSMEM>>>(
        xr_p, w1_p, xz_p, BL, 2 * DINNER, DMODEL);

    // 2) fused conv+silu -> xc, xcT; gate -> gateT
    conv_prep<<<dim3(SEQLEN / 32, DINNER / 32, BATCH), 256>>>(conv_w, conv_b);

    // 3) xp = xc @ x_proj_w^T (K-split 2 + combine)
    xproj_kernel<<<dim3(BL / XR, 1, 2), 256>>>(x_proj_w);
    xp_combine<<<(BL * XPROJ_ROWS + 255) / 256, 256>>>();

    // 4) dtT (softplus, transposed)
    prep_dtT<<<dim3(SEQLEN / 32, DINNER / 32, BATCH), 256>>>(dt_proj_w, dt_proj_b);

    // 5) chunked selective scan -> ygT
    scan_pass1<<<(NPAIR * (NCHUNK - 1)) / 8, 256>>>(A_log);
    scan_pass2<<<(NPAIR * 32) / 256, 256>>>(A_log);
    scan_pass3<<<(NPAIR * NCHUNK) / 8, 256>>>(A_log, D_param);

    // 6) out = ygT^T @ out_proj_w^T, split-K=4 (A read directly from ygT)
    gemm_tf32_At<<<dim3(DMODEL / 128, BL / 128, 4), 128, GSMEM2>>>(
        ygT_p, w2_p, pk_p, pk_p + (size_t)BL * DMODEL, xc_p, xr_p,
        DMODEL, DINNER, DINNER / 4);
    {
        int n4 = (BL * DMODEL) / 4;
        add4_kernel<<<(n4 + 255) / 256, 256>>>(pk_p, pk_p + (size_t)BL * DMODEL,
                                               xc_p, xr_p, out, n4);
    }
}

// round 16
// speedup vs baseline: 1.0761x; 1.0001x over previous
#include <cuda_runtime.h>
#include <math.h>
#include <stdint.h>

#define BATCH   2
#define SEQLEN  1024
#define DMODEL  1024
#define DINNER  2048
#define NSTATE  16
#define BL      (BATCH*SEQLEN)      // 2048 rows
#define XPROJ_ROWS 33               // 1 dt + 16 B + 16 C
#define NCHUNK  8
#define LC      (SEQLEN/NCHUNK)     // 128
#define NPAIR   (BATCH*DINNER/2)    // 2048 warp-pairs

// ---------------- scratch (no allocs allowed) ----------------
__device__ float g_xz[(size_t)BL * 2 * DINNER];   // [bl][4096]
__device__ float g_xc[(size_t)BL * DINNER];       // conv out; later split-K partial 2
__device__ float g_xp[(size_t)BL * XPROJ_ROWS];
__device__ float g_xp2[(size_t)BL * XPROJ_ROWS];  // xproj K-split partial
__device__ float g_pk[(size_t)BL * DINNER];       // split-K partials 0,1
// transposed [b][d][t] scan streams
__device__ float g_dtT[(size_t)BL * DINNER];
__device__ float g_xcT[(size_t)BL * DINNER];
__device__ float g_gateT[(size_t)BL * DINNER];
__device__ float g_ygT[(size_t)BL * DINNER];
// TF32-rounded copies of GEMM inputs (g_xr later split-K partial 3)
__device__ float g_xr[(size_t)BL * DMODEL];
__device__ float g_w1r[(size_t)(2*DINNER) * DMODEL];
__device__ float g_w2r[(size_t)DMODEL * DINNER];
// chunked-scan scratch
__device__ float g_S [(size_t)NPAIR * (NCHUNK-1) * 2];
__device__ float g_Lh[(size_t)NPAIR * (NCHUNK-1) * 32];
__device__ float g_Hin[(size_t)NPAIR * NCHUNK * 32];

__device__ __forceinline__ unsigned f2tf32(float x) {
    unsigned r;
    asm("cvt.rna.tf32.f32 %0, %1;" : "=r"(r) : "f"(x));
    return r;
}

// ---------------- fused RNA pre-rounding ----------------
#define XN4   ((BL * DMODEL) / 4)
#define W1N4  ((2 * DINNER * DMODEL) / 4)
#define W2N4  ((DMODEL * DINNER) / 4)
__global__ __launch_bounds__(256) void rna_round_all(const float* __restrict__ x,
                                                     const float* __restrict__ w1,
                                                     const float* __restrict__ w2) {
    int i = blockIdx.x * 256 + threadIdx.x;
    const float4* src;
    float4* dst;
    int off;
    if (i < XN4)              { src = (const float4*)x;  dst = (float4*)g_xr;  off = i; }
    else if (i < XN4 + W1N4)  { src = (const float4*)w1; dst = (float4*)g_w1r; off = i - XN4; }
    else if (i < XN4 + W1N4 + W2N4) { src = (const float4*)w2; dst = (float4*)g_w2r; off = i - XN4 - W1N4; }
    else return;
    float4 v = src[off];
    v.x = __uint_as_float(f2tf32(v.x));
    v.y = __uint_as_float(f2tf32(v.y));
    v.z = __uint_as_float(f2tf32(v.z));
    v.w = __uint_as_float(f2tf32(v.w));
    dst[off] = v;
}

// ---------------- add pass for split-K=4 ----------------
__global__ __launch_bounds__(256) void add4_kernel(const float* __restrict__ p0,
                                                   const float* __restrict__ p1,
                                                   const float* __restrict__ p2,
                                                   const float* __restrict__ p3,
                                                   float* __restrict__ out, int n4) {
    int i = blockIdx.x * 256 + threadIdx.x;
    if (i >= n4) return;
    float4 a = ((const float4*)p0)[i];
    float4 b = ((const float4*)p1)[i];
    float4 c = ((const float4*)p2)[i];
    float4 d = ((const float4*)p3)[i];
    ((float4*)out)[i] = make_float4((a.x + b.x) + (c.x + d.x),
                                    (a.y + b.y) + (c.y + d.y),
                                    (a.z + b.z) + (c.z + d.z),
                                    (a.w + b.w) + (c.w + d.w));
}

// ================= common GEMM helpers =================
#define BK      16
#define KPITCH  20
#define ATILE   (128 * KPITCH)
#define STAGE_F (2 * ATILE)
#define STAGES  4
#define GSMEM   (STAGES * STAGE_F * 4)   // 81920 B

__device__ __forceinline__ uint32_t smem_u32(const void* p) {
    uint32_t a;
    asm("{ .reg .u64 t; cvta.to.shared.u64 t, %1; cvt.u32.u64 %0, t; }" : "=r"(a) : "l"(p));
    return a;
}
__device__ __forceinline__ void cp_async16(uint32_t dst, const void* src) {
    asm volatile("cp.async.cg.shared.global [%0], [%1], 16;" :: "r"(dst), "l"(src));
}
__device__ __forceinline__ void cp_commit() {
    asm volatile("cp.async.commit_group;");
}
template <int N>
__device__ __forceinline__ void cp_wait() {
    asm volatile("cp.async.wait_group %0;" :: "n"(N));
}
__device__ __forceinline__ void mma_tf32(float* c, const unsigned* a, const unsigned* b) {
    asm volatile(
        "mma.sync.aligned.m16n8k8.row.col.f32.tf32.tf32.f32 "
        "{%0,%1,%2,%3}, {%4,%5,%6,%7}, {%8,%9}, {%0,%1,%2,%3};\n"
        : "+f"(c[0]), "+f"(c[1]), "+f"(c[2]), "+f"(c[3])
        : "r"(a[0]), "r"(a[1]), "r"(a[2]), "r"(a[3]), "r"(b[0]), "r"(b[1]));
}

// ================= GEMM1 (A row-major): 128 threads, 64x64 warp tiles =================
__global__ __launch_bounds__(128, 2) void gemm_tf32_pipe(const float* __restrict__ A,
                                                         const float* __restrict__ B,
                                                         float* __restrict__ C,
                                                         int M, int N, int K) {
    extern __shared__ float smem[];
    const uint32_t smem_base = smem_u32(smem);

    const int t    = threadIdx.x;
    const int lane = t & 31;
    const int warp = t >> 5;           // 0..3
    const int g    = lane >> 2;
    const int tk   = lane & 3;
    const int wm   = (warp >> 1) * 64;
    const int wn   = (warp & 1) * 64;

    const int rowBase = blockIdx.y * 128;
    const int colBase = blockIdx.x * 128;
    const float* Ag = A + (size_t)rowBase * K;
    const float* Bg = B + (size_t)colBase * K;

    const int lrow0 = t >> 2;          // 0..31
    const int lch   = (t & 3) * 4;
    const int NKT   = K / BK;

    float acc[32][4];
#pragma unroll
    for (int i = 0; i < 32; i++)
#pragma unroll
        for (int j = 0; j < 4; j++) acc[i][j] = 0.f;

    auto load_stage = [&](int s, int kt) {
        const int koff = kt * BK;
        const uint32_t As = smem_base + (uint32_t)(s * STAGE_F) * 4u;
        const uint32_t Bs = As + (uint32_t)ATILE * 4u;
#pragma unroll
        for (int rep = 0; rep < 4; rep++) {
            const int row = lrow0 + rep * 32;
            const uint32_t doff = (uint32_t)(row * KPITCH + lch) * 4u;
            cp_async16(As + doff, Ag + (size_t)row * K + koff + lch);
            cp_async16(Bs + doff, Bg + (size_t)row * K + koff + lch);
        }
    };

    load_stage(0, 0); cp_commit();
    if (NKT > 1) load_stage(1, 1);
    cp_commit();
    if (NKT > 2) load_stage(2, 2);
    cp_commit();

    for (int kt = 0; kt < NKT; kt++) {
        cp_wait<2>();
        __syncthreads();

        if (kt + 3 < NKT) load_stage((kt + 3) & 3, kt + 3);
        cp_commit();

        const float* As = smem + (kt & 3) * STAGE_F;
        const float* Bs = As + ATILE;

#pragma unroll
        for (int ks = 0; ks < 2; ks++) {
            const int k0 = ks * 8;
            unsigned a[4][4], b[8][2];
#pragma unroll
            for (int i = 0; i < 4; i++) {
                const int m0 = wm + i * 16;
                a[i][0] = __float_as_uint(As[(m0 + g)     * KPITCH + k0 + tk]);
                a[i][1] = __float_as_uint(As[(m0 + g + 8) * KPITCH + k0 + tk]);
                a[i][2] = __float_as_uint(As[(m0 + g)     * KPITCH + k0 + tk + 4]);
                a[i][3] = __float_as_uint(As[(m0 + g + 8) * KPITCH + k0 + tk + 4]);
            }
#pragma unroll
            for (int j = 0; j < 8; j++) {
                const int n0 = wn + j * 8;
                b[j][0] = __float_as_uint(Bs[(n0 + g) * KPITCH + k0 + tk]);
                b[j][1] = __float_as_uint(Bs[(n0 + g) * KPITCH + k0 + tk + 4]);
            }
#pragma unroll
            for (int i = 0; i < 4; i++)
#pragma unroll
                for (int j = 0; j < 8; j++)
                    mma_tf32(acc[i * 8 + j], a[i], b[j]);
        }
        __syncthreads();
    }

#pragma unroll
    for (int i = 0; i < 4; i++) {
#pragma unroll
        for (int j = 0; j < 8; j++) {
            const float* c = acc[i * 8 + j];
            const int row0 = rowBase + wm + i * 16 + g;
            const int col  = colBase + wn + j * 8 + tk * 2;
            *(float2*)(C + (size_t)row0 * N + col)       = make_float2(c[0], c[1]);
            *(float2*)(C + (size_t)(row0 + 8) * N + col) = make_float2(c[2], c[3]);
        }
    }
}

// ================= GEMM2: A K-major from ygT, split-K=4, 128 threads =================
#define A2PITCH 136
#define A2TILE_B (BK * A2PITCH * 4)              // 8704 B
#define B2TILE_B (128 * KPITCH * 4)              // 10240 B
#define STAGE2_B (A2TILE_B + B2TILE_B)           // 18944 B
#define GSMEM2   (STAGES * STAGE2_B)             // 75776 B

__global__ __launch_bounds__(128, 2) void gemm_tf32_At(const float* __restrict__ AT,
                                                       const float* __restrict__ B,
                                                       float* __restrict__ C0,
                                                       float* __restrict__ C1,
                                                       float* __restrict__ C2,
                                                       float* __restrict__ C3,
                                                       int N, int K, int klen) {
    extern __shared__ float smem[];
    const uint32_t smem_base = smem_u32(smem);

    const int t    = threadIdx.x;
    const int lane = t & 31;
    const int warp = t >> 5;
    const int g    = lane >> 2;
    const int tk   = lane & 3;
    const int wm   = (warp >> 1) * 64;
    const int wn   = (warp & 1) * 64;

    const int rowBase = blockIdx.y * 128;
    const int colBase = blockIdx.x * 128;
    const int kbase   = blockIdx.z * klen;
    float* C = (blockIdx.z == 0) ? C0 : (blockIdx.z == 1) ? C1 : (blockIdx.z == 2) ? C2 : C3;

    const int b      = rowBase >> 10;
    const int t_base = rowBase & (SEQLEN - 1);
    const float* AgT = AT + ((size_t)(b * DINNER + kbase)) * SEQLEN + t_base;
    const float* Bg  = B + (size_t)colBase * K + kbase;

    const int lrow0 = t >> 2;
    const int lch   = (t & 3) * 4;
    const int NKT   = klen / BK;

    float acc[32][4];
#pragma unroll
    for (int i = 0; i < 32; i++)
#pragma unroll
        for (int j = 0; j < 4; j++) acc[i][j] = 0.f;

    auto load_stage = [&](int s, int kt) {
        const int koff = kt * BK;
        const uint32_t As = smem_base + (uint32_t)(s * STAGE2_B);
        const uint32_t Bs = As + (uint32_t)A2TILE_B;
        // A: 512 16B chunks (16 k-rows x 32 chunks of 4 t) over 128 threads
#pragma unroll
        for (int rep = 0; rep < 4; rep++) {
            const int c = t + rep * 128;
            const int k = c >> 5;
            const int off = (c & 31) * 4;
            cp_async16(As + (uint32_t)(k * A2PITCH + off) * 4u,
                       AgT + (size_t)(koff + k) * SEQLEN + off);
        }
        // B
#pragma unroll
        for (int rep = 0; rep < 4; rep++) {
            const int row = lrow0 + rep * 32;
            cp_async16(Bs + (uint32_t)(row * KPITCH + lch) * 4u,
                       Bg + (size_t)row * K + koff + lch);
        }
    };

    load_stage(0, 0); cp_commit();
    if (NKT > 1) load_stage(1, 1);
    cp_commit();
    if (NKT > 2) load_stage(2, 2);
    cp_commit();

    for (int kt = 0; kt < NKT; kt++) {
        cp_wait<2>();
        __syncthreads();

        if (kt + 3 < NKT) load_stage((kt + 3) & 3, kt + 3);
        cp_commit();

        const float* As = (const float*)((const char*)smem + (kt & 3) * STAGE2_B);
        const float* Bs = (const float*)((const char*)As + A2TILE_B);

#pragma unroll
        for (int ks = 0; ks < 2; ks++) {
            const int k0 = ks * 8;
            unsigned a[4][4], b[8][2];
#pragma unroll
            for (int i = 0; i < 4; i++) {
                const int m0 = wm + i * 16;
                a[i][0] = __float_as_uint(As[(k0 + tk)     * A2PITCH + m0 + g]);
                a[i][1] = __float_as_uint(As[(k0 + tk)     * A2PITCH + m0 + g + 8]);
                a[i][2] = __float_as_uint(As[(k0 + tk + 4) * A2PITCH + m0 + g]);
                a[i][3] = __float_as_uint(As[(k0 + tk + 4) * A2PITCH + m0 + g + 8]);
            }
#pragma unroll
            for (int j = 0; j < 8; j++) {
                const int n0 = wn + j * 8;
                b[j][0] = __float_as_uint(Bs[(n0 + g) * KPITCH + k0 + tk]);
                b[j][1] = __float_as_uint(Bs[(n0 + g) * KPITCH + k0 + tk + 4]);
            }
#pragma unroll
            for (int i = 0; i < 4; i++)
#pragma unroll
                for (int j = 0; j < 8; j++)
                    mma_tf32(acc[i * 8 + j], a[i], b[j]);
        }
        __syncthreads();
    }

#pragma unroll
    for (int i = 0; i < 4; i++) {
#pragma unroll
        for (int j = 0; j < 8; j++) {
            const float* c = acc[i * 8 + j];
            const int row0 = rowBase + wm + i * 16 + g;
            const int col  = colBase + wn + j * 8 + tk * 2;
            *(float2*)(C + (size_t)row0 * N + col)       = make_float2(c[0], c[1]);
            *(float2*)(C + (size_t)(row0 + 8) * N + col) = make_float2(c[2], c[3]);
        }
    }
}

// ---------------- fused conv + SiLU -> xc, xcT; gate = silu(z) -> gateT ----------------
__global__ __launch_bounds__(256) void conv_prep(const float* __restrict__ conv_w,
                                                 const float* __restrict__ conv_b) {
    __shared__ float xt[36][33];
    __shared__ float tt[32][33];
    const int b  = blockIdx.z;
    const int l0 = blockIdx.x * 32;
    const int d0 = blockIdx.y * 32;
    const int tx = threadIdx.x & 31;
    const int ty = threadIdx.x >> 5;
    const int d  = d0 + tx;

    for (int r = ty; r < 35; r += 8) {
        const int l = l0 + r - 3;
        xt[r][tx] = (l >= 0) ? g_xz[(size_t)(b * SEQLEN + l) * (2 * DINNER) + d] : 0.f;
    }
    __syncthreads();

    const float w0 = conv_w[d * 4 + 0], w1 = conv_w[d * 4 + 1];
    const float w2 = conv_w[d * 4 + 2], w3 = conv_w[d * 4 + 3];
    const float cb = conv_b[d];
#pragma unroll
    for (int k4 = 0; k4 < 4; k4++) {
        const int lr = ty + k4 * 8;
        float acc = cb;
        acc = fmaf(w0, xt[lr][tx], acc);
        acc = fmaf(w1, xt[lr + 1][tx], acc);
        acc = fmaf(w2, xt[lr + 2][tx], acc);
        acc = fmaf(w3, xt[lr + 3][tx], acc);
        const float xc = acc / (1.f + __expf(-acc));
        g_xc[(size_t)(b * SEQLEN + l0 + lr) * DINNER + d] = xc;
        tt[lr][tx] = xc;
    }
    __syncthreads();
#pragma unroll
    for (int k4 = 0; k4 < 4; k4++) {
        const int dd = d0 + ty + k4 * 8;
        g_xcT[(size_t)(b * DINNER + dd) * SEQLEN + l0 + tx] = tt[tx][ty + k4 * 8];
    }
    __syncthreads();
#pragma unroll
    for (int k4 = 0; k4 < 4; k4++) {
        const int lr = ty + k4 * 8;
        const float z = g_xz[(size_t)(b * SEQLEN + l0 + lr) * (2 * DINNER) + DINNER + d];
        tt[lr][tx] = z / (1.f + __expf(-z));
    }
    __syncthreads();
#pragma unroll
    for (int k4 = 0; k4 < 4; k4++) {
        const int dd = d0 + ty + k4 * 8;
        g_gateT[(size_t)(b * DINNER + dd) * SEQLEN + l0 + tx] = tt[tx][ty + k4 * 8];
    }
}

// ---------------- x_proj: K-split 2, 8 rows/block, 32 KB smem ----------------
#define XR 8
#define XKH (DINNER / 2)                  // 1024
__global__ __launch_bounds__(256) void xproj_kernel(const float* __restrict__ W) {
    __shared__ float sx[XR * XKH];        // 32 KB
    const int bl0  = blockIdx.x * XR;
    const int koff = blockIdx.z * XKH;
    float* outp = blockIdx.z ? g_xp2 : g_xp;

    for (int i = threadIdx.x; i < XR * (XKH / 4); i += 256) {
        const int q = i >> 8;
        const int c = i & 255;
        ((float4*)sx)[i] = ((const float4*)(g_xc + (size_t)(bl0 + q) * DINNER + koff))[c];
    }
    __syncthreads();

    const int warp = threadIdx.x >> 5, lane = threadIdx.x & 31;
    for (int j = warp; j < XPROJ_ROWS; j += 8) {
        const float4* wr = (const float4*)(W + (size_t)j * DINNER + koff);
        float s[XR];
#pragma unroll
        for (int q = 0; q < XR; q++) s[q] = 0.f;
        for (int i = lane; i < XKH / 4; i += 32) {
            float4 w = __ldg(wr + i);
#pragma unroll
            for (int q = 0; q < XR; q++) {
                float4 xv = ((const float4*)(sx + q * XKH))[i];
                s[q] = fmaf(xv.x, w.x, fmaf(xv.y, w.y, fmaf(xv.z, w.z, fmaf(xv.w, w.w, s[q]))));
            }
        }
#pragma unroll
        for (int o = 16; o; o >>= 1)
#pragma unroll
            for (int q = 0; q < XR; q++)
                s[q] += __shfl_xor_sync(0xffffffffu, s[q], o);
        if (lane == 0) {
#pragma unroll
            for (int q = 0; q < XR; q++)
                outp[(size_t)(bl0 + q) * XPROJ_ROWS + j] = s[q];
        }
    }
}

__global__ __launch_bounds__(256) void xp_combine() {
    int i = blockIdx.x * 256 + threadIdx.x;
    if (i < BL * XPROJ_ROWS) g_xp[i] += g_xp2[i];
}

// ---------------- dtT = softplus(dtr*w + b), transposed ----------------
__global__ __launch_bounds__(256) void prep_dtT(const float* __restrict__ dtw,
                                                const float* __restrict__ dtb) {
    __shared__ float tile[32][33];
    const int b  = blockIdx.z;
    const int l0 = blockIdx.x * 32;
    const int d0 = blockIdx.y * 32;
    const int tx = threadIdx.x & 31;
    const int ty = threadIdx.x >> 5;
    const float w = dtw[d0 + tx], bb = dtb[d0 + tx];
#pragma unroll
    for (int k = 0; k < 4; k++) {
        const int l = l0 + ty + k * 8;
        const float dtr = g_xp[(size_t)(b * SEQLEN + l) * XPROJ_ROWS];
        const float xv = fmaf(dtr, w, bb);
        tile[ty + k * 8][tx] = fmaxf(xv, 0.f) + __logf(1.f + __expf(-fabsf(xv)));
    }
    __syncthreads();
#pragma unroll
    for (int k = 0; k < 4; k++) {
        const int dd = d0 + ty + k * 8;
        g_dtT[(size_t)(b * DINNER + dd) * SEQLEN + l0 + tx] = tile[tx][ty + k * 8];
    }
}

// ================= chunked selective scan (transposed streams) =================
#define SUNR 8

__device__ __forceinline__ void ld8(const float* p, int t0, float* v) {
    float4 a = __ldg((const float4*)(p + t0));
    float4 b = __ldg((const float4*)(p + t0 + 4));
    v[0] = a.x; v[1] = a.y; v[2] = a.z; v[3] = a.w;
    v[4] = b.x; v[5] = b.y; v[6] = b.z; v[7] = b.w;
}

__global__ __launch_bounds__(256) void scan_pass1(const float* __restrict__ A_log) {
    const int wg = blockIdx.x * 8 + (threadIdx.x >> 5);
    const int lane  = threadIdx.x & 31;
    const int group = lane >> 4;
    const int n     = lane & 15;
    const int pair  = wg / (NCHUNK - 1);
    const int chunk = wg - pair * (NCHUNK - 1);
    const int p2 = pair * 2;
    const int d  = (p2 & (DINNER - 1)) + group;
    const int b  = p2 >> 11;

    const float Acoef = -expf(A_log[d * NSTATE + n]);

    const float* xpb  = g_xp  + (size_t)b * SEQLEN * XPROJ_ROWS;
    const float* dtpT = g_dtT + (size_t)(b * DINNER + d) * SEQLEN;
    const float* xcpT = g_xcT + (size_t)(b * DINNER + d) * SEQLEN;

    float h = 0.f, S = 0.f;
    const int tb = chunk * LC;
    for (int t0 = tb; t0 < tb + LC; t0 += SUNR) {
        float dtv[SUNR], xcv[SUNR], Bv[SUNR];
        ld8(dtpT, t0, dtv);
        ld8(xcpT, t0, xcv);
#pragma unroll
        for (int u = 0; u < SUNR; u++)
            Bv[u] = __ldg(xpb + (size_t)(t0 + u) * XPROJ_ROWS + 1 + n);
#pragma unroll
        for (int u = 0; u < SUNR; u++) {
            const float dA = __expf(dtv[u] * Acoef);
            h = fmaf(dA, h, dtv[u] * xcv[u] * Bv[u]);
            S += dtv[u];
        }
    }
    g_Lh[(size_t)(pair * (NCHUNK - 1) + chunk) * 32 + lane] = h;
    if (n == 0)
        g_S[(size_t)(pair * (NCHUNK - 1) + chunk) * 2 + group] = S;
}

__global__ __launch_bounds__(256) void scan_pass2(const float* __restrict__ A_log) {
    const int gid  = blockIdx.x * 256 + threadIdx.x;
    const int pair = gid >> 5;
    const int lane = gid & 31;
    const int group = lane >> 4;
    const int n     = lane & 15;
    const int d = ((pair * 2) & (DINNER - 1)) + group;
    const float Acoef = -expf(A_log[d * NSTATE + n]);

    float hin = 0.f;
    g_Hin[(size_t)(pair * NCHUNK) * 32 + lane] = 0.f;
#pragma unroll
    for (int c = 0; c < NCHUNK - 1; c++) {
        const float S = g_S[(size_t)(pair * (NCHUNK - 1) + c) * 2 + group];
        const float L = g_Lh[(size_t)(pair * (NCHUNK - 1) + c) * 32 + lane];
        hin = fmaf(__expf(Acoef * S), hin, L);
        g_Hin[(size_t)(pair * NCHUNK + c + 1) * 32 + lane] = hin;
    }
}

__global__ __launch_bounds__(256) void scan_pass3(const float* __restrict__ A_log,
                                                  const float* __restrict__ D_param) {
    const int wg = blockIdx.x * 8 + (threadIdx.x >> 5);
    const int lane  = threadIdx.x & 31;
    const int group = lane >> 4;
    const int n     = lane & 15;
    const int pair  = wg >> 3;
    const int chunk = wg & 7;
    const int p2 = pair * 2;
    const int d  = (p2 & (DINNER - 1)) + group;
    const int b  = p2 >> 11;

    const float Acoef = -expf(A_log[d * NSTATE + n]);
    const float Dp    = D_param[d];

    const float* xpb  = g_xp    + (size_t)b * SEQLEN * XPROJ_ROWS;
    const float* dtpT = g_dtT   + (size_t)(b * DINNER + d) * SEQLEN;
    const float* xcpT = g_xcT   + (size_t)(b * DINNER + d) * SEQLEN;
    const float* gpT  = g_gateT + (size_t)(b * DINNER + d) * SEQLEN;
    float*       ygpT = g_ygT   + (size_t)(b * DINNER + d) * SEQLEN;

    float h = g_Hin[(size_t)(pair * NCHUNK + chunk) * 32 + lane];
    const int tb = chunk * LC;
    for (int t0 = tb; t0 < tb + LC; t0 += SUNR) {
        float dtv[SUNR], xcv[SUNR], gv[SUNR], Bv[SUNR], Cv[SUNR];
        ld8(dtpT, t0, dtv);
        ld8(xcpT, t0, xcv);
        ld8(gpT,  t0, gv);
#pragma unroll
        for (int u = 0; u < SUNR; u++) {
            const float* xpr = xpb + (size_t)(t0 + u) * XPROJ_ROWS;
            Bv[u] = __ldg(xpr + 1 + n);
            Cv[u] = __ldg(xpr + 1 + NSTATE + n);
        }
        float y[SUNR];
#pragma unroll
        for (int u = 0; u < SUNR; u++) {
            const float dA = __expf(dtv[u] * Acoef);
            h = fmaf(dA, h, dtv[u] * xcv[u] * Bv[u]);
            y[u] = h * Cv[u];
        }
#pragma unroll
        for (int u = 0; u < SUNR; u++) {
            y[u] += __shfl_xor_sync(0xffffffffu, y[u], 8);
            y[u] += __shfl_xor_sync(0xffffffffu, y[u], 4);
            y[u] += __shfl_xor_sync(0xffffffffu, y[u], 2);
            y[u] += __shfl_xor_sync(0xffffffffu, y[u], 1);
        }
        if (n == 0) {
            float o[SUNR];
#pragma unroll
            for (int u = 0; u < SUNR; u++) {
                const float yy = fmaf(xcv[u], Dp, y[u]);
                o[u] = __uint_as_float(f2tf32(yy * gv[u]));
            }
            *(float4*)(ygpT + t0)     = make_float4(o[0], o[1], o[2], o[3]);
            *(float4*)(ygpT + t0 + 4) = make_float4(o[4], o[5], o[6], o[7]);
        }
    }
}

// ---------------- launch ----------------
extern "C" void kernel_launch(void* const* d_in, const int* in_sizes, int n_in,
                              void* d_out, int out_size) {
    const float* x          = (const float*)d_in[0];
    const float* in_proj_w  = (const float*)d_in[1];
    const float* conv_w     = (const float*)d_in[2];
    const float* conv_b     = (const float*)d_in[3];
    const float* x_proj_w   = (const float*)d_in[4];
    const float* dt_proj_w  = (const float*)d_in[5];
    const float* dt_proj_b  = (const float*)d_in[6];
    const float* A_log      = (const float*)d_in[7];
    const float* D_param    = (const float*)d_in[8];
    const float* out_proj_w = (const float*)d_in[9];
    float* out = (float*)d_out;

    float *xz_p = nullptr, *xr_p = nullptr, *w1_p = nullptr, *w2_p = nullptr,
          *xc_p = nullptr, *pk_p = nullptr, *ygT_p = nullptr;
    cudaGetSymbolAddress((void**)&xz_p, g_xz);
    cudaGetSymbolAddress((void**)&xr_p, g_xr);
    cudaGetSymbolAddress((void**)&w1_p, g_w1r);
    cudaGetSymbolAddress((void**)&w2_p, g_w2r);
    cudaGetSymbolAddress((void**)&xc_p, g_xc);
    cudaGetSymbolAddress((void**)&pk_p, g_pk);
    cudaGetSymbolAddress((void**)&ygT_p, g_ygT);

    static int attr_set = 0;
    if (!attr_set) {
        cudaFuncSetAttribute(gemm_tf32_pipe, cudaFuncAttributeMaxDynamicSharedMemorySize, GSMEM);
        cudaFuncSetAttribute(gemm_tf32_At, cudaFuncAttributeMaxDynamicSharedMemorySize, GSMEM2);
        attr_set = 1;
    }

    // 0) RNA-round all GEMM inputs
    {
        int total = XN4 + W1N4 + W2N4;
        rna_round_all<<<(total + 255) / 256, 256>>>(x, in_proj_w, out_proj_w);
    }

    // 1) xz = x @ in_proj_w^T
    gemm_tf32_pipe<<<dim3((2 * DINNER) / 128, BL / 128), 128, GSMEM>>>(
        xr_p, w1_p, xz_p, BL, 2 * DINNER, DMODEL);

    // 2) fused conv+silu -> xc, xcT; gate -> gateT
    conv_prep<<<dim3(SEQLEN / 32, DINNER / 32, BATCH), 256>>>(conv_w, conv_b);

    // 3) xp = xc @ x_proj_w^T (K-split 2 + combine)
    xproj_kernel<<<dim3(BL / XR, 1, 2), 256>>>(x_proj_w);
    xp_combine<<<(BL * XPROJ_ROWS + 255) / 256, 256>>>();

    // 4) dtT (softplus, transposed)
    prep_dtT<<<dim3(SEQLEN / 32, DINNER / 32, BATCH), 256>>>(dt_proj_w, dt_proj_b);

    // 5) chunked selective scan -> ygT
    scan_pass1<<<(NPAIR * (NCHUNK - 1)) / 8, 256>>>(A_log);
    scan_pass2<<<(NPAIR * 32) / 256, 256>>>(A_log);
    scan_pass3<<<(NPAIR * NCHUNK) / 8, 256>>>(A_log, D_param);

    // 6) out = ygT^T @ out_proj_w^T, split-K=4 (A read directly from ygT)
    gemm_tf32_At<<<dim3(DMODEL / 128, BL / 128, 4), 128, GSMEM2>>>(
        ygT_p, w2_p, pk_p, pk_p + (size_t)BL * DMODEL, xc_p, xr_p,
        DMODEL, DINNER, DINNER / 4);
    {
        int n4 = (BL * DMODEL) / 4;
        add4_kernel<<<(n4 + 255) / 256, 256>>>(pk_p, pk_p + (size_t)BL * DMODEL,
                                               xc_p, xr_p, out, n4);
    }
}